// round 7
// baseline (speedup 1.0000x reference)
#include <cuda_runtime.h>
#include <cuda_bf16.h>
#include <stdint.h>

#define NN 50000
#define EE 800000
#define DD 256
#define LL 3
#define GG 512
#define ND (LL * DD)   // 768

// ---------------------------------------------------------------------------
// Device scratch (ping-pong h buffers: no cross-CTA RAW hazard within a layer)
// ---------------------------------------------------------------------------
__device__ float g_ha[(size_t)NN * DD];
__device__ float g_hb[(size_t)NN * DD];
__device__ int   g_deg[NN];
__device__ int   g_off[NN + 1];
__device__ int   g_cur[NN];
__device__ int   g_csr[EE];
__device__ int   g_counts[GG];
__device__ __nv_bfloat16 g_wt_hi[6 * 256 * 256];
__device__ __nv_bfloat16 g_wt_lo[6 * 256 * 256];

// ---------------------------------------------------------------------------
// PTX helpers (sm_80-era only)
// ---------------------------------------------------------------------------
__device__ __forceinline__ uint32_t smem_u32(const void* p) {
    uint32_t a;
    asm("{ .reg .u64 t; cvta.to.shared.u64 t, %1; cvt.u32.u64 %0, t; }" : "=r"(a) : "l"(p));
    return a;
}
__device__ __forceinline__ void ldsm4(uint32_t* r, uint32_t addr) {
    asm volatile("ldmatrix.sync.aligned.m8n8.x4.shared.b16 {%0,%1,%2,%3}, [%4];"
        : "=r"(r[0]), "=r"(r[1]), "=r"(r[2]), "=r"(r[3]) : "r"(addr));
}
__device__ __forceinline__ void mma_bf16(float* d, const uint32_t* a, const uint32_t* b) {
    asm volatile("mma.sync.aligned.m16n8k16.row.col.f32.bf16.bf16.f32 "
        "{%0,%1,%2,%3}, {%4,%5,%6,%7}, {%8,%9}, {%0,%1,%2,%3};"
        : "+f"(d[0]), "+f"(d[1]), "+f"(d[2]), "+f"(d[3])
        : "r"(a[0]), "r"(a[1]), "r"(a[2]), "r"(a[3]), "r"(b[0]), "r"(b[1]));
}
#define CP_ASYNC16(dst, src) \
    asm volatile("cp.async.cg.shared.global [%0], [%1], 16;" :: "r"(dst), "l"(src) : "memory")
#define CP_COMMIT() asm volatile("cp.async.commit_group;" ::: "memory")
#define CP_WAIT1()  asm volatile("cp.async.wait_group 1;" ::: "memory")
#define CP_WAIT0()  asm volatile("cp.async.wait_group 0;" ::: "memory")

// ---------------------------------------------------------------------------
// Small utility kernels
// ---------------------------------------------------------------------------
__global__ void zero_f_kernel(float* __restrict__ p, int n) {
    int i = blockIdx.x * blockDim.x + threadIdx.x;
    if (i < n) p[i] = 0.0f;
}
__global__ void zero_i_kernel(int* __restrict__ p, int n) {
    int i = blockIdx.x * blockDim.x + threadIdx.x;
    if (i < n) p[i] = 0;
}
__global__ void count_graph_kernel(const int* __restrict__ batch, int* __restrict__ counts) {
    int i = blockIdx.x * blockDim.x + threadIdx.x;
    if (i < NN) atomicAdd(&counts[batch[i]], 1);
}

// Transpose + bf16 hi/lo split of the 6 weight matrices. Output [N][K] row-major.
__global__ void wprep_kernel(const float* __restrict__ Ws1, const float* __restrict__ Ws2,
                             __nv_bfloat16* __restrict__ wh, __nv_bfloat16* __restrict__ wl) {
    int i = blockIdx.x * blockDim.x + threadIdx.x;
    if (i >= 6 * 65536) return;
    int mat = i >> 16;
    int rem = i & 65535;
    int k = rem >> 8, n = rem & 255;
    const float* W = (mat < 3) ? (Ws1 + (size_t)mat * 65536) : (Ws2 + (size_t)(mat - 3) * 65536);
    float x = W[k * 256 + n];
    __nv_bfloat16 hi = __float2bfloat16(x);
    __nv_bfloat16 lo = __float2bfloat16(x - __bfloat162float(hi));
    size_t o = ((size_t)mat << 16) + (size_t)n * 256 + k;
    wh[o] = hi;
    wl[o] = lo;
}

// ---------------------------------------------------------------------------
// CSR build
// ---------------------------------------------------------------------------
__global__ void deg_kernel(const int* __restrict__ dst, int* __restrict__ deg) {
    int e = blockIdx.x * blockDim.x + threadIdx.x;
    if (e < EE) atomicAdd(&deg[dst[e]], 1);
}

__global__ void scan_kernel(const int* __restrict__ deg, int* __restrict__ off,
                            int* __restrict__ cur) {
    __shared__ int warp_sums[32];
    __shared__ int carry_s;
    const int tid = threadIdx.x;
    const int lane = tid & 31;
    const int wid = tid >> 5;
    if (tid == 0) carry_s = 0;
    __syncthreads();

    for (int base = 0; base < NN; base += 1024) {
        int i = base + tid;
        int v = (i < NN) ? deg[i] : 0;
        int incl = v;
#pragma unroll
        for (int o = 1; o < 32; o <<= 1) {
            int t = __shfl_up_sync(0xFFFFFFFFu, incl, o);
            if (lane >= o) incl += t;
        }
        if (lane == 31) warp_sums[wid] = incl;
        __syncthreads();
        if (wid == 0) {
            int ws = warp_sums[lane];
#pragma unroll
            for (int o = 1; o < 32; o <<= 1) {
                int t = __shfl_up_sync(0xFFFFFFFFu, ws, o);
                if (lane >= o) ws += t;
            }
            warp_sums[lane] = ws;
        }
        __syncthreads();
        int excl = incl - v + (wid > 0 ? warp_sums[wid - 1] : 0) + carry_s;
        if (i < NN) { off[i] = excl; cur[i] = excl; }
        __syncthreads();
        if (tid == 1023) carry_s = excl + v;
        __syncthreads();
    }
    if (tid == 0) off[NN] = carry_s;
}

__global__ void fill_kernel(const int* __restrict__ src, const int* __restrict__ dst,
                            int* __restrict__ cur, int* __restrict__ csr) {
    int e = blockIdx.x * blockDim.x + threadIdx.x;
    if (e >= EE) return;
    int d = dst[e];
    int p = atomicAdd(&cur[d], 1);
    csr[p] = src[e];
}

// ---------------------------------------------------------------------------
// Fused layer kernel: gather -> GEMM1 -> (t in smem) -> GEMM2 -> h + node_embed
// 512 threads (16 warps), CTA owns 128 rows x all 256 cols.
// Reads hin (previous layer buffer), writes hout (other buffer) -> no race.
// ---------------------------------------------------------------------------
#define AT_STR 528
#define OFF_ALO 67584              // 128*528
#define OFF_B 135168               // 2*67584
#define B_HALF 20480               // 256 rows * 80B
#define B_BUFSZ 40960
#define FUSED_SMEM 217088          // 135168 + 2*40960

__device__ __forceinline__ void issue_b_chunk(uint32_t sb,
        const __nv_bfloat16* __restrict__ Wh, const __nv_bfloat16* __restrict__ Wl,
        int kb, int buf, int tid) {
#pragma unroll
    for (int j = 0; j < 4; j++) {
        int i = tid + j * 512;            // 0..2047
        int half = i >> 10;
        int rem = i & 1023;
        int n = rem >> 2;                 // 0..255
        int seg = rem & 3;                // 16B segment of 64B row
        const __nv_bfloat16* src = (half ? Wl : Wh) + (size_t)n * DD + kb + seg * 8;
        uint32_t dst = sb + OFF_B + (uint32_t)buf * B_BUFSZ + (uint32_t)half * B_HALF
                     + (uint32_t)n * 80 + (uint32_t)seg * 16;
        CP_ASYNC16(dst, src);
    }
    CP_COMMIT();
}

__device__ __forceinline__ ushort2 split_hi(float a, float b) {
    ushort2 r;
    r.x = __bfloat16_as_ushort(__float2bfloat16(a));
    r.y = __bfloat16_as_ushort(__float2bfloat16(b));
    return r;
}
__device__ __forceinline__ ushort2 split_lo(float a, float b, ushort2 hi) {
    ushort2 r;
    r.x = __bfloat16_as_ushort(__float2bfloat16(a - __bfloat162float(__ushort_as_bfloat16(hi.x))));
    r.y = __bfloat16_as_ushort(__float2bfloat16(b - __bfloat162float(__ushort_as_bfloat16(hi.y))));
    return r;
}

template <bool TO_SMEM>
__device__ __forceinline__ void gemm_phase(char* smem, uint32_t sb,
        const __nv_bfloat16* __restrict__ Wh, const __nv_bfloat16* __restrict__ Wl,
        const float* __restrict__ bias, int bm,
        float* __restrict__ hout, float* __restrict__ ne) {
    const int tid = threadIdx.x;
    const int lane = tid & 31;
    const int w = tid >> 5;
    const int wm = (w & 3) * 32;
    const int wn = (w >> 2) * 64;
    const int frow = (lane & 7) + ((lane & 8) ? 8 : 0);
    const int fkc  = ((lane & 16) ? 8 : 0);
    const int brow = (lane & 7) + ((lane & 16) ? 8 : 0);
    const int bkc  = ((lane & 8) ? 8 : 0);

    float acc[2][8][4];
#pragma unroll
    for (int mi = 0; mi < 2; mi++)
#pragma unroll
        for (int nj = 0; nj < 8; nj++)
#pragma unroll
            for (int q = 0; q < 4; q++) acc[mi][nj][q] = 0.0f;

    for (int c = 0; c < 8; c++) {
        if (c < 7) {
            issue_b_chunk(sb, Wh, Wl, (c + 1) * 32, (c + 1) & 1, tid);
            CP_WAIT1();
        } else {
            CP_WAIT0();
        }
        __syncthreads();

        const uint32_t bh_base = sb + OFF_B + (uint32_t)(c & 1) * B_BUFSZ;
        const uint32_t bl_base = bh_base + B_HALF;
#pragma unroll
        for (int ks = 0; ks < 2; ks++) {
            const int kA = c * 32 + ks * 16;
            uint32_t ah[2][4], al[2][4];
#pragma unroll
            for (int mi = 0; mi < 2; mi++) {
                uint32_t o = (uint32_t)(wm + mi * 16 + frow) * AT_STR + (uint32_t)(kA + fkc) * 2;
                ldsm4(ah[mi], sb + o);
                ldsm4(al[mi], sb + OFF_ALO + o);
            }
#pragma unroll
            for (int p = 0; p < 4; p++) {
                uint32_t o = (uint32_t)(wn + p * 16 + brow) * 80 + (uint32_t)(ks * 16 + bkc) * 2;
                uint32_t th[4], tl[4];
                ldsm4(th, bh_base + o);
                ldsm4(tl, bl_base + o);
                uint32_t b0h[2] = {th[0], th[1]}, b1h[2] = {th[2], th[3]};
                uint32_t b0l[2] = {tl[0], tl[1]}, b1l[2] = {tl[2], tl[3]};
#pragma unroll
                for (int mi = 0; mi < 2; mi++) {
                    mma_bf16(acc[mi][2 * p],     ah[mi], b0h);
                    mma_bf16(acc[mi][2 * p],     ah[mi], b0l);
                    mma_bf16(acc[mi][2 * p],     al[mi], b0h);
                    mma_bf16(acc[mi][2 * p + 1], ah[mi], b1h);
                    mma_bf16(acc[mi][2 * p + 1], ah[mi], b1l);
                    mma_bf16(acc[mi][2 * p + 1], al[mi], b1h);
                }
            }
        }
        __syncthreads();   // protect buffer reuse by next chunk's cp.async
    }

    // epilogue
    const int g2 = lane >> 2;
    const int tg2 = (lane & 3) * 2;
#pragma unroll
    for (int mi = 0; mi < 2; mi++) {
        const int r0l = wm + mi * 16 + g2;
        const int r1l = r0l + 8;
#pragma unroll
        for (int nj = 0; nj < 8; nj++) {
            const int col = wn + nj * 8 + tg2;
            float b0 = __ldg(&bias[col]);
            float b1 = __ldg(&bias[col + 1]);
            float v00 = fmaxf(acc[mi][nj][0] + b0, 0.0f);
            float v01 = fmaxf(acc[mi][nj][1] + b1, 0.0f);
            float v10 = fmaxf(acc[mi][nj][2] + b0, 0.0f);
            float v11 = fmaxf(acc[mi][nj][3] + b1, 0.0f);
            if (TO_SMEM) {
                uint32_t o0 = (uint32_t)r0l * AT_STR + (uint32_t)col * 2;
                uint32_t o1 = (uint32_t)r1l * AT_STR + (uint32_t)col * 2;
                ushort2 h0 = split_hi(v00, v01);
                ushort2 h1 = split_hi(v10, v11);
                *(ushort2*)(smem + o0) = h0;
                *(ushort2*)(smem + o1) = h1;
                *(ushort2*)(smem + OFF_ALO + o0) = split_lo(v00, v01, h0);
                *(ushort2*)(smem + OFF_ALO + o1) = split_lo(v10, v11, h1);
            } else {
                const int r0 = bm + r0l, r1 = bm + r1l;
                if (r0 < NN) {
                    float2 v = make_float2(v00, v01);
                    *(float2*)(hout + (size_t)r0 * DD + col) = v;
                    *(float2*)(ne + (size_t)r0 * ND + col) = v;
                }
                if (r1 < NN) {
                    float2 v = make_float2(v10, v11);
                    *(float2*)(hout + (size_t)r1 * DD + col) = v;
                    *(float2*)(ne + (size_t)r1 * ND + col) = v;
                }
            }
        }
    }
}

__global__ __launch_bounds__(512, 1)
void fused_layer_kernel(const float* __restrict__ hin,
                        const int* __restrict__ off, const int* __restrict__ csr,
                        const __nv_bfloat16* __restrict__ W1h, const __nv_bfloat16* __restrict__ W1l,
                        const float* __restrict__ b1,
                        const __nv_bfloat16* __restrict__ W2h, const __nv_bfloat16* __restrict__ W2l,
                        const float* __restrict__ b2,
                        float* __restrict__ hout, float* __restrict__ ne) {
    extern __shared__ char smem[];
    const uint32_t sb = smem_u32(smem);
    const int tid = threadIdx.x;
    const int lane = tid & 31;
    const int w = tid >> 5;
    const int bm = blockIdx.x * 128;

    // start W1 chunk0 early
    issue_b_chunk(sb, W1h, W1l, 0, 0, tid);

    // gather: agg row = hin[row] + sum of neighbor rows; split bf16 hi/lo into A tile
    const float4* __restrict__ h4 = (const float4*)hin;
#pragma unroll 1
    for (int rr = 0; rr < 8; rr++) {
        const int rl = w * 8 + rr;
        const int gr = bm + rl;
        float4 a0 = make_float4(0.f, 0.f, 0.f, 0.f);
        float4 a1 = make_float4(0.f, 0.f, 0.f, 0.f);
        if (gr < NN) {
            a0 = __ldg(&h4[(size_t)gr * 64 + lane]);
            a1 = __ldg(&h4[(size_t)gr * 64 + lane + 32]);
            int j = __ldg(&off[gr]);
            const int je = __ldg(&off[gr + 1]);
            for (; j + 2 <= je; j += 2) {
                int s0 = __ldg(&csr[j]);
                int s1 = __ldg(&csr[j + 1]);
                float4 v0 = __ldg(&h4[(size_t)s0 * 64 + lane]);
                float4 u0 = __ldg(&h4[(size_t)s0 * 64 + lane + 32]);
                float4 v1 = __ldg(&h4[(size_t)s1 * 64 + lane]);
                float4 u1 = __ldg(&h4[(size_t)s1 * 64 + lane + 32]);
                a0.x += v0.x + v1.x; a0.y += v0.y + v1.y;
                a0.z += v0.z + v1.z; a0.w += v0.w + v1.w;
                a1.x += u0.x + u1.x; a1.y += u0.y + u1.y;
                a1.z += u0.z + u1.z; a1.w += u0.w + u1.w;
            }
            if (j < je) {
                int s0 = __ldg(&csr[j]);
                float4 v0 = __ldg(&h4[(size_t)s0 * 64 + lane]);
                float4 u0 = __ldg(&h4[(size_t)s0 * 64 + lane + 32]);
                a0.x += v0.x; a0.y += v0.y; a0.z += v0.z; a0.w += v0.w;
                a1.x += u0.x; a1.y += u0.y; a1.z += u0.z; a1.w += u0.w;
            }
        }
        // split + store (cols 4*lane.. and 4*(lane+32)..)
        char* base = smem + (uint32_t)rl * AT_STR + (uint32_t)lane * 8;
        ushort2 h0a = split_hi(a0.x, a0.y);
        ushort2 h0b = split_hi(a0.z, a0.w);
        ushort4 hh0; hh0.x = h0a.x; hh0.y = h0a.y; hh0.z = h0b.x; hh0.w = h0b.y;
        ushort2 l0a = split_lo(a0.x, a0.y, h0a);
        ushort2 l0b = split_lo(a0.z, a0.w, h0b);
        ushort4 ll0; ll0.x = l0a.x; ll0.y = l0a.y; ll0.z = l0b.x; ll0.w = l0b.y;
        *(ushort4*)(base) = hh0;
        *(ushort4*)(base + OFF_ALO) = ll0;
        ushort2 h1a = split_hi(a1.x, a1.y);
        ushort2 h1b = split_hi(a1.z, a1.w);
        ushort4 hh1; hh1.x = h1a.x; hh1.y = h1a.y; hh1.z = h1b.x; hh1.w = h1b.y;
        ushort2 l1a = split_lo(a1.x, a1.y, h1a);
        ushort2 l1b = split_lo(a1.z, a1.w, h1b);
        ushort4 ll1; ll1.x = l1a.x; ll1.y = l1a.y; ll1.z = l1b.x; ll1.w = l1b.y;
        *(ushort4*)(base + 256) = hh1;
        *(ushort4*)(base + OFF_ALO + 256) = ll1;
    }
    __syncthreads();

    // phase 1: t = relu(agg @ W1 + b1) -> smem (overwrites A tile)
    gemm_phase<true>(smem, sb, W1h, W1l, b1, bm, nullptr, nullptr);
    __syncthreads();

    // phase 2: h = relu(t @ W2 + b2) -> gmem
    issue_b_chunk(sb, W2h, W2l, 0, 0, tid);
    gemm_phase<false>(smem, sb, W2h, W2l, b2, bm, hout, ne);
}

// ---------------------------------------------------------------------------
// Pooling with run compression (batch sorted)
// ---------------------------------------------------------------------------
__global__ __launch_bounds__(256)
void pool_kernel(const int* __restrict__ batch, const float* __restrict__ ne,
                 float* __restrict__ gev) {
    const int c = blockIdx.y * 256 + threadIdx.x;
    const int n0 = blockIdx.x * 128;
    int n1 = n0 + 128; if (n1 > NN) n1 = NN;

    int g = __ldg(&batch[n0]);
    float acc = 0.0f;
    for (int n = n0; n < n1; n++) {
        int gn = __ldg(&batch[n]);
        if (gn != g) {
            atomicAdd(&gev[(size_t)g * ND + c], acc);
            acc = 0.0f;
            g = gn;
        }
        acc += __ldg(&ne[(size_t)n * ND + c]);
    }
    atomicAdd(&gev[(size_t)g * ND + c], acc);
}

__global__ void divide_kernel(float* __restrict__ gev, const int* __restrict__ counts) {
    int i = blockIdx.x * blockDim.x + threadIdx.x;
    if (i >= GG * ND) return;
    int g = i / ND;
    int cnt = counts[g];
    gev[i] *= 1.0f / (float)(cnt > 0 ? cnt : 1);
}

// ---------------------------------------------------------------------------
// Launch
// ---------------------------------------------------------------------------
extern "C" void kernel_launch(void* const* d_in, const int* in_sizes, int n_in,
                              void* d_out, int out_size) {
    const float* x          = (const float*)d_in[0];
    const int*   edge_index = (const int*)d_in[1];
    const int*   batch      = (const int*)d_in[2];
    const float* Ws1        = (const float*)d_in[3];
    const float* bs1        = (const float*)d_in[4];
    const float* Ws2        = (const float*)d_in[5];
    const float* bs2        = (const float*)d_in[6];

    float* out = (float*)d_out;
    float* graph_embed = out;
    float* node_embed  = out + (size_t)GG * ND;

    float* ha;   cudaGetSymbolAddress((void**)&ha,   g_ha);
    float* hb;   cudaGetSymbolAddress((void**)&hb,   g_hb);
    int* deg;    cudaGetSymbolAddress((void**)&deg,  g_deg);
    int* off;    cudaGetSymbolAddress((void**)&off,  g_off);
    int* cur;    cudaGetSymbolAddress((void**)&cur,  g_cur);
    int* csr;    cudaGetSymbolAddress((void**)&csr,  g_csr);
    int* counts; cudaGetSymbolAddress((void**)&counts, g_counts);
    __nv_bfloat16* wth; cudaGetSymbolAddress((void**)&wth, g_wt_hi);
    __nv_bfloat16* wtl; cudaGetSymbolAddress((void**)&wtl, g_wt_lo);

    cudaFuncSetAttribute(fused_layer_kernel, cudaFuncAttributeMaxDynamicSharedMemorySize, FUSED_SMEM);

    const int* esrc = edge_index;
    const int* edst = edge_index + EE;

    // CSR build
    zero_i_kernel<<<(NN + 255) / 256, 256>>>(deg, NN);
    deg_kernel<<<(EE + 255) / 256, 256>>>(edst, deg);
    scan_kernel<<<1, 1024>>>(deg, off, cur);
    fill_kernel<<<(EE + 255) / 256, 256>>>(esrc, edst, cur, csr);

    // weight prep
    wprep_kernel<<<(6 * 65536 + 255) / 256, 256>>>(Ws1, Ws2, wth, wtl);

    // graph counts + zero graph_embed
    zero_i_kernel<<<(GG + 255) / 256, 256>>>(counts, GG);
    count_graph_kernel<<<(NN + 255) / 256, 256>>>(batch, counts);
    zero_f_kernel<<<(GG * ND + 255) / 256, 256>>>(graph_embed, GG * ND);

    const int mtiles = (NN + 127) / 128;   // 391

    // ping-pong h buffers: x -> ha -> hb -> ha
    const float* hin = x;
    float* houts[LL] = {ha, hb, ha};
    for (int l = 0; l < LL; l++) {
        fused_layer_kernel<<<mtiles, 512, FUSED_SMEM>>>(
            hin, off, csr,
            wth + (size_t)l * 65536, wtl + (size_t)l * 65536, bs1 + l * DD,
            wth + (size_t)(3 + l) * 65536, wtl + (size_t)(3 + l) * 65536, bs2 + l * DD,
            houts[l], node_embed + (size_t)l * DD);
        hin = houts[l];
    }

    dim3 pgrid((NN + 127) / 128, LL);
    pool_kernel<<<pgrid, 256>>>(batch, node_embed, graph_embed);
    divide_kernel<<<(GG * ND + 255) / 256, 256>>>(graph_embed, counts);
}

// round 8
// speedup vs baseline: 1.0224x; 1.0224x over previous
#include <cuda_runtime.h>
#include <cuda_bf16.h>
#include <stdint.h>

#define NN 50000
#define EE 800000
#define DD 256
#define LL 3
#define GG 512
#define ND (LL * DD)   // 768

// ---------------------------------------------------------------------------
// Device scratch (ping-pong h buffers: no cross-CTA RAW hazard within a layer)
// ---------------------------------------------------------------------------
__device__ float g_ha[(size_t)NN * DD];
__device__ float g_hb[(size_t)NN * DD];
__device__ int   g_deg[NN];
__device__ int   g_off[NN + 1];
__device__ int   g_cur[NN];
__device__ int   g_csr[EE];
__device__ int   g_counts[GG];
__device__ __nv_bfloat16 g_wt_hi[6 * 256 * 256];
__device__ __nv_bfloat16 g_wt_lo[6 * 256 * 256];

// ---------------------------------------------------------------------------
// PTX helpers (sm_80-era only)
// ---------------------------------------------------------------------------
__device__ __forceinline__ uint32_t smem_u32(const void* p) {
    uint32_t a;
    asm("{ .reg .u64 t; cvta.to.shared.u64 t, %1; cvt.u32.u64 %0, t; }" : "=r"(a) : "l"(p));
    return a;
}
__device__ __forceinline__ void ldsm4(uint32_t* r, uint32_t addr) {
    asm volatile("ldmatrix.sync.aligned.m8n8.x4.shared.b16 {%0,%1,%2,%3}, [%4];"
        : "=r"(r[0]), "=r"(r[1]), "=r"(r[2]), "=r"(r[3]) : "r"(addr));
}
__device__ __forceinline__ void mma_bf16(float* d, const uint32_t* a, const uint32_t* b) {
    asm volatile("mma.sync.aligned.m16n8k16.row.col.f32.bf16.bf16.f32 "
        "{%0,%1,%2,%3}, {%4,%5,%6,%7}, {%8,%9}, {%0,%1,%2,%3};"
        : "+f"(d[0]), "+f"(d[1]), "+f"(d[2]), "+f"(d[3])
        : "r"(a[0]), "r"(a[1]), "r"(a[2]), "r"(a[3]), "r"(b[0]), "r"(b[1]));
}
#define CP_ASYNC16(dst, src) \
    asm volatile("cp.async.cg.shared.global [%0], [%1], 16;" :: "r"(dst), "l"(src) : "memory")
#define CP_COMMIT() asm volatile("cp.async.commit_group;" ::: "memory")
#define CP_WAIT1()  asm volatile("cp.async.wait_group 1;" ::: "memory")
#define CP_WAIT0()  asm volatile("cp.async.wait_group 0;" ::: "memory")

// ---------------------------------------------------------------------------
// Setup kernels (exactly 5 launches before the first fused kernel)
// ---------------------------------------------------------------------------
// 1) zero deg, counts, graph_embed
__global__ void init_zero_kernel(int* __restrict__ deg, int* __restrict__ counts,
                                 float* __restrict__ gev) {
    int i = blockIdx.x * blockDim.x + threadIdx.x;
    if (i < NN) deg[i] = 0;
    if (i < GG) counts[i] = 0;
    if (i < GG * ND) gev[i] = 0.0f;
}

// 2) edge degree histogram + graph size histogram
__global__ void deg_count_kernel(const int* __restrict__ dst, const int* __restrict__ batch,
                                 int* __restrict__ deg, int* __restrict__ counts) {
    int i = blockIdx.x * blockDim.x + threadIdx.x;
    if (i < EE) atomicAdd(&deg[dst[i]], 1);
    if (i < NN) atomicAdd(&counts[batch[i]], 1);
}

// 3) single-block exclusive scan
__global__ void scan_kernel(const int* __restrict__ deg, int* __restrict__ off,
                            int* __restrict__ cur) {
    __shared__ int warp_sums[32];
    __shared__ int carry_s;
    const int tid = threadIdx.x;
    const int lane = tid & 31;
    const int wid = tid >> 5;
    if (tid == 0) carry_s = 0;
    __syncthreads();

    for (int base = 0; base < NN; base += 1024) {
        int i = base + tid;
        int v = (i < NN) ? deg[i] : 0;
        int incl = v;
#pragma unroll
        for (int o = 1; o < 32; o <<= 1) {
            int t = __shfl_up_sync(0xFFFFFFFFu, incl, o);
            if (lane >= o) incl += t;
        }
        if (lane == 31) warp_sums[wid] = incl;
        __syncthreads();
        if (wid == 0) {
            int ws = warp_sums[lane];
#pragma unroll
            for (int o = 1; o < 32; o <<= 1) {
                int t = __shfl_up_sync(0xFFFFFFFFu, ws, o);
                if (lane >= o) ws += t;
            }
            warp_sums[lane] = ws;
        }
        __syncthreads();
        int excl = incl - v + (wid > 0 ? warp_sums[wid - 1] : 0) + carry_s;
        if (i < NN) { off[i] = excl; cur[i] = excl; }
        __syncthreads();
        if (tid == 1023) carry_s = excl + v;
        __syncthreads();
    }
    if (tid == 0) off[NN] = carry_s;
}

// 4) CSR fill
__global__ void fill_kernel(const int* __restrict__ src, const int* __restrict__ dst,
                            int* __restrict__ cur, int* __restrict__ csr) {
    int e = blockIdx.x * blockDim.x + threadIdx.x;
    if (e >= EE) return;
    int d = dst[e];
    int p = atomicAdd(&cur[d], 1);
    csr[p] = src[e];
}

// 5) transpose + bf16 hi/lo split of the 6 weight matrices; output [N][K] row-major
__global__ void wprep_kernel(const float* __restrict__ Ws1, const float* __restrict__ Ws2,
                             __nv_bfloat16* __restrict__ wh, __nv_bfloat16* __restrict__ wl) {
    int i = blockIdx.x * blockDim.x + threadIdx.x;
    if (i >= 6 * 65536) return;
    int mat = i >> 16;
    int rem = i & 65535;
    int k = rem >> 8, n = rem & 255;
    const float* W = (mat < 3) ? (Ws1 + (size_t)mat * 65536) : (Ws2 + (size_t)(mat - 3) * 65536);
    float x = W[k * 256 + n];
    __nv_bfloat16 hi = __float2bfloat16(x);
    __nv_bfloat16 lo = __float2bfloat16(x - __bfloat162float(hi));
    size_t o = ((size_t)mat << 16) + (size_t)n * 256 + k;
    wh[o] = hi;
    wl[o] = lo;
}

// ---------------------------------------------------------------------------
// Fused layer kernel: gather -> GEMM1 -> (t in smem) -> GEMM2 -> h + node_embed
// ---------------------------------------------------------------------------
#define AT_STR 528
#define OFF_ALO 67584              // 128*528
#define OFF_B 135168               // 2*67584
#define B_HALF 20480               // 256 rows * 80B
#define B_BUFSZ 40960
#define FUSED_SMEM 217088          // 135168 + 2*40960

__device__ __forceinline__ void issue_b_chunk(uint32_t sb,
        const __nv_bfloat16* __restrict__ Wh, const __nv_bfloat16* __restrict__ Wl,
        int kb, int buf, int tid) {
#pragma unroll
    for (int j = 0; j < 4; j++) {
        int i = tid + j * 512;            // 0..2047
        int half = i >> 10;
        int rem = i & 1023;
        int n = rem >> 2;                 // 0..255
        int seg = rem & 3;                // 16B segment of 64B row
        const __nv_bfloat16* src = (half ? Wl : Wh) + (size_t)n * DD + kb + seg * 8;
        uint32_t dst = sb + OFF_B + (uint32_t)buf * B_BUFSZ + (uint32_t)half * B_HALF
                     + (uint32_t)n * 80 + (uint32_t)seg * 16;
        CP_ASYNC16(dst, src);
    }
    CP_COMMIT();
}

__device__ __forceinline__ ushort2 split_hi(float a, float b) {
    ushort2 r;
    r.x = __bfloat16_as_ushort(__float2bfloat16(a));
    r.y = __bfloat16_as_ushort(__float2bfloat16(b));
    return r;
}
__device__ __forceinline__ ushort2 split_lo(float a, float b, ushort2 hi) {
    ushort2 r;
    r.x = __bfloat16_as_ushort(__float2bfloat16(a - __bfloat162float(__ushort_as_bfloat16(hi.x))));
    r.y = __bfloat16_as_ushort(__float2bfloat16(b - __bfloat162float(__ushort_as_bfloat16(hi.y))));
    return r;
}

template <bool TO_SMEM>
__device__ __forceinline__ void gemm_phase(char* smem, uint32_t sb,
        const __nv_bfloat16* __restrict__ Wh, const __nv_bfloat16* __restrict__ Wl,
        const float* __restrict__ bias, int bm,
        float* __restrict__ hout, float* __restrict__ ne) {
    const int tid = threadIdx.x;
    const int lane = tid & 31;
    const int w = tid >> 5;
    const int wm = (w & 3) * 32;
    const int wn = (w >> 2) * 64;
    const int frow = (lane & 7) + ((lane & 8) ? 8 : 0);
    const int fkc  = ((lane & 16) ? 8 : 0);
    const int brow = (lane & 7) + ((lane & 16) ? 8 : 0);
    const int bkc  = ((lane & 8) ? 8 : 0);

    float acc[2][8][4];
#pragma unroll
    for (int mi = 0; mi < 2; mi++)
#pragma unroll
        for (int nj = 0; nj < 8; nj++)
#pragma unroll
            for (int q = 0; q < 4; q++) acc[mi][nj][q] = 0.0f;

    for (int c = 0; c < 8; c++) {
        if (c < 7) {
            issue_b_chunk(sb, Wh, Wl, (c + 1) * 32, (c + 1) & 1, tid);
            CP_WAIT1();
        } else {
            CP_WAIT0();
        }
        __syncthreads();

        const uint32_t bh_base = sb + OFF_B + (uint32_t)(c & 1) * B_BUFSZ;
        const uint32_t bl_base = bh_base + B_HALF;
#pragma unroll
        for (int ks = 0; ks < 2; ks++) {
            const int kA = c * 32 + ks * 16;
            uint32_t ah[2][4], al[2][4];
#pragma unroll
            for (int mi = 0; mi < 2; mi++) {
                uint32_t o = (uint32_t)(wm + mi * 16 + frow) * AT_STR + (uint32_t)(kA + fkc) * 2;
                ldsm4(ah[mi], sb + o);
                ldsm4(al[mi], sb + OFF_ALO + o);
            }
#pragma unroll
            for (int p = 0; p < 4; p++) {
                uint32_t o = (uint32_t)(wn + p * 16 + brow) * 80 + (uint32_t)(ks * 16 + bkc) * 2;
                uint32_t th[4], tl[4];
                ldsm4(th, bh_base + o);
                ldsm4(tl, bl_base + o);
                uint32_t b0h[2] = {th[0], th[1]}, b1h[2] = {th[2], th[3]};
                uint32_t b0l[2] = {tl[0], tl[1]}, b1l[2] = {tl[2], tl[3]};
#pragma unroll
                for (int mi = 0; mi < 2; mi++) {
                    mma_bf16(acc[mi][2 * p],     ah[mi], b0h);
                    mma_bf16(acc[mi][2 * p],     ah[mi], b0l);
                    mma_bf16(acc[mi][2 * p],     al[mi], b0h);
                    mma_bf16(acc[mi][2 * p + 1], ah[mi], b1h);
                    mma_bf16(acc[mi][2 * p + 1], ah[mi], b1l);
                    mma_bf16(acc[mi][2 * p + 1], al[mi], b1h);
                }
            }
        }
        __syncthreads();   // protect buffer reuse by next chunk's cp.async
    }

    // epilogue
    const int g2 = lane >> 2;
    const int tg2 = (lane & 3) * 2;
#pragma unroll
    for (int mi = 0; mi < 2; mi++) {
        const int r0l = wm + mi * 16 + g2;
        const int r1l = r0l + 8;
#pragma unroll
        for (int nj = 0; nj < 8; nj++) {
            const int col = wn + nj * 8 + tg2;
            float b0 = __ldg(&bias[col]);
            float b1 = __ldg(&bias[col + 1]);
            float v00 = fmaxf(acc[mi][nj][0] + b0, 0.0f);
            float v01 = fmaxf(acc[mi][nj][1] + b1, 0.0f);
            float v10 = fmaxf(acc[mi][nj][2] + b0, 0.0f);
            float v11 = fmaxf(acc[mi][nj][3] + b1, 0.0f);
            if (TO_SMEM) {
                uint32_t o0 = (uint32_t)r0l * AT_STR + (uint32_t)col * 2;
                uint32_t o1 = (uint32_t)r1l * AT_STR + (uint32_t)col * 2;
                ushort2 h0 = split_hi(v00, v01);
                ushort2 h1 = split_hi(v10, v11);
                *(ushort2*)(smem + o0) = h0;
                *(ushort2*)(smem + o1) = h1;
                *(ushort2*)(smem + OFF_ALO + o0) = split_lo(v00, v01, h0);
                *(ushort2*)(smem + OFF_ALO + o1) = split_lo(v10, v11, h1);
            } else {
                const int r0 = bm + r0l, r1 = bm + r1l;
                if (r0 < NN) {
                    float2 v = make_float2(v00, v01);
                    *(float2*)(hout + (size_t)r0 * DD + col) = v;
                    *(float2*)(ne + (size_t)r0 * ND + col) = v;
                }
                if (r1 < NN) {
                    float2 v = make_float2(v10, v11);
                    *(float2*)(hout + (size_t)r1 * DD + col) = v;
                    *(float2*)(ne + (size_t)r1 * ND + col) = v;
                }
            }
        }
    }
}

__global__ __launch_bounds__(512, 1)
void fused_layer_kernel(const float* __restrict__ hin,
                        const int* __restrict__ off, const int* __restrict__ csr,
                        const __nv_bfloat16* __restrict__ W1h, const __nv_bfloat16* __restrict__ W1l,
                        const float* __restrict__ b1,
                        const __nv_bfloat16* __restrict__ W2h, const __nv_bfloat16* __restrict__ W2l,
                        const float* __restrict__ b2,
                        float* __restrict__ hout, float* __restrict__ ne) {
    extern __shared__ char smem[];
    const uint32_t sb = smem_u32(smem);
    const int tid = threadIdx.x;
    const int lane = tid & 31;
    const int w = tid >> 5;
    const int bm = blockIdx.x * 128;

    // start W1 chunk0 early (overlaps with gather)
    issue_b_chunk(sb, W1h, W1l, 0, 0, tid);

    // gather: agg row = hin[row] + sum of neighbor rows.
    // Warp-per-row; CSR indices fetched coalesced (one load / 32 edges) and
    // broadcast via shfl; feature loads unrolled x4 for MLP.
    const float4* __restrict__ h4 = (const float4*)hin;
#pragma unroll 1
    for (int rr = 0; rr < 8; rr++) {
        const int rl = w * 8 + rr;
        const int gr = bm + rl;
        float4 a0 = make_float4(0.f, 0.f, 0.f, 0.f);
        float4 a1 = make_float4(0.f, 0.f, 0.f, 0.f);
        if (gr < NN) {
            a0 = __ldg(&h4[(size_t)gr * 64 + lane]);
            a1 = __ldg(&h4[(size_t)gr * 64 + lane + 32]);
            int j = __ldg(&off[gr]);
            const int je = __ldg(&off[gr + 1]);
            while (j < je) {
                const int cnt = min(32, je - j);
                int myidx = (lane < cnt) ? __ldg(&csr[j + lane]) : 0;
                int e = 0;
                for (; e + 4 <= cnt; e += 4) {
                    int s0 = __shfl_sync(0xFFFFFFFFu, myidx, e);
                    int s1 = __shfl_sync(0xFFFFFFFFu, myidx, e + 1);
                    int s2 = __shfl_sync(0xFFFFFFFFu, myidx, e + 2);
                    int s3 = __shfl_sync(0xFFFFFFFFu, myidx, e + 3);
                    float4 v0 = __ldg(&h4[(size_t)s0 * 64 + lane]);
                    float4 u0 = __ldg(&h4[(size_t)s0 * 64 + lane + 32]);
                    float4 v1 = __ldg(&h4[(size_t)s1 * 64 + lane]);
                    float4 u1 = __ldg(&h4[(size_t)s1 * 64 + lane + 32]);
                    float4 v2 = __ldg(&h4[(size_t)s2 * 64 + lane]);
                    float4 u2 = __ldg(&h4[(size_t)s2 * 64 + lane + 32]);
                    float4 v3 = __ldg(&h4[(size_t)s3 * 64 + lane]);
                    float4 u3 = __ldg(&h4[(size_t)s3 * 64 + lane + 32]);
                    a0.x += v0.x + v1.x; a0.y += v0.y + v1.y;
                    a0.z += v0.z + v1.z; a0.w += v0.w + v1.w;
                    a0.x += v2.x + v3.x; a0.y += v2.y + v3.y;
                    a0.z += v2.z + v3.z; a0.w += v2.w + v3.w;
                    a1.x += u0.x + u1.x; a1.y += u0.y + u1.y;
                    a1.z += u0.z + u1.z; a1.w += u0.w + u1.w;
                    a1.x += u2.x + u3.x; a1.y += u2.y + u3.y;
                    a1.z += u2.z + u3.z; a1.w += u2.w + u3.w;
                }
                for (; e < cnt; e++) {
                    int s0 = __shfl_sync(0xFFFFFFFFu, myidx, e);
                    float4 v0 = __ldg(&h4[(size_t)s0 * 64 + lane]);
                    float4 u0 = __ldg(&h4[(size_t)s0 * 64 + lane + 32]);
                    a0.x += v0.x; a0.y += v0.y; a0.z += v0.z; a0.w += v0.w;
                    a1.x += u0.x; a1.y += u0.y; a1.z += u0.z; a1.w += u0.w;
                }
                j += cnt;
            }
        }
        // split + store (cols 4*lane.. and 4*(lane+32)..)
        char* base = smem + (uint32_t)rl * AT_STR + (uint32_t)lane * 8;
        ushort2 h0a = split_hi(a0.x, a0.y);
        ushort2 h0b = split_hi(a0.z, a0.w);
        ushort4 hh0; hh0.x = h0a.x; hh0.y = h0a.y; hh0.z = h0b.x; hh0.w = h0b.y;
        ushort2 l0a = split_lo(a0.x, a0.y, h0a);
        ushort2 l0b = split_lo(a0.z, a0.w, h0b);
        ushort4 ll0; ll0.x = l0a.x; ll0.y = l0a.y; ll0.z = l0b.x; ll0.w = l0b.y;
        *(ushort4*)(base) = hh0;
        *(ushort4*)(base + OFF_ALO) = ll0;
        ushort2 h1a = split_hi(a1.x, a1.y);
        ushort2 h1b = split_hi(a1.z, a1.w);
        ushort4 hh1; hh1.x = h1a.x; hh1.y = h1a.y; hh1.z = h1b.x; hh1.w = h1b.y;
        ushort2 l1a = split_lo(a1.x, a1.y, h1a);
        ushort2 l1b = split_lo(a1.z, a1.w, h1b);
        ushort4 ll1; ll1.x = l1a.x; ll1.y = l1a.y; ll1.z = l1b.x; ll1.w = l1b.y;
        *(ushort4*)(base + 256) = hh1;
        *(ushort4*)(base + OFF_ALO + 256) = ll1;
    }
    __syncthreads();

    // phase 1: t = relu(agg @ W1 + b1) -> smem (overwrites A tile)
    gemm_phase<true>(smem, sb, W1h, W1l, b1, bm, nullptr, nullptr);
    __syncthreads();

    // phase 2: h = relu(t @ W2 + b2) -> gmem
    issue_b_chunk(sb, W2h, W2l, 0, 0, tid);
    gemm_phase<false>(smem, sb, W2h, W2l, b2, bm, hout, ne);
}

// ---------------------------------------------------------------------------
// Pooling with run compression (batch sorted)
// ---------------------------------------------------------------------------
__global__ __launch_bounds__(256)
void pool_kernel(const int* __restrict__ batch, const float* __restrict__ ne,
                 float* __restrict__ gev) {
    const int c = blockIdx.y * 256 + threadIdx.x;
    const int n0 = blockIdx.x * 128;
    int n1 = n0 + 128; if (n1 > NN) n1 = NN;

    int g = __ldg(&batch[n0]);
    float acc = 0.0f;
    for (int n = n0; n < n1; n++) {
        int gn = __ldg(&batch[n]);
        if (gn != g) {
            atomicAdd(&gev[(size_t)g * ND + c], acc);
            acc = 0.0f;
            g = gn;
        }
        acc += __ldg(&ne[(size_t)n * ND + c]);
    }
    atomicAdd(&gev[(size_t)g * ND + c], acc);
}

__global__ void divide_kernel(float* __restrict__ gev, const int* __restrict__ counts) {
    int i = blockIdx.x * blockDim.x + threadIdx.x;
    if (i >= GG * ND) return;
    int g = i / ND;
    int cnt = counts[g];
    gev[i] *= 1.0f / (float)(cnt > 0 ? cnt : 1);
}

// ---------------------------------------------------------------------------
// Launch
// ---------------------------------------------------------------------------
extern "C" void kernel_launch(void* const* d_in, const int* in_sizes, int n_in,
                              void* d_out, int out_size) {
    const float* x          = (const float*)d_in[0];
    const int*   edge_index = (const int*)d_in[1];
    const int*   batch      = (const int*)d_in[2];
    const float* Ws1        = (const float*)d_in[3];
    const float* bs1        = (const float*)d_in[4];
    const float* Ws2        = (const float*)d_in[5];
    const float* bs2        = (const float*)d_in[6];

    float* out = (float*)d_out;
    float* graph_embed = out;
    float* node_embed  = out + (size_t)GG * ND;

    float* ha;   cudaGetSymbolAddress((void**)&ha,   g_ha);
    float* hb;   cudaGetSymbolAddress((void**)&hb,   g_hb);
    int* deg;    cudaGetSymbolAddress((void**)&deg,  g_deg);
    int* off;    cudaGetSymbolAddress((void**)&off,  g_off);
    int* cur;    cudaGetSymbolAddress((void**)&cur,  g_cur);
    int* csr;    cudaGetSymbolAddress((void**)&csr,  g_csr);
    int* counts; cudaGetSymbolAddress((void**)&counts, g_counts);
    __nv_bfloat16* wth; cudaGetSymbolAddress((void**)&wth, g_wt_hi);
    __nv_bfloat16* wtl; cudaGetSymbolAddress((void**)&wtl, g_wt_lo);

    cudaFuncSetAttribute(fused_layer_kernel, cudaFuncAttributeMaxDynamicSharedMemorySize, FUSED_SMEM);

    const int* esrc = edge_index;
    const int* edst = edge_index + EE;

    // ---- exactly 5 setup launches (ncu -s 5 -c 1 captures fused kernel) ----
    init_zero_kernel<<<(GG * ND + 255) / 256, 256>>>(deg, counts, graph_embed);
    deg_count_kernel<<<(EE + 255) / 256, 256>>>(edst, batch, deg, counts);
    scan_kernel<<<1, 1024>>>(deg, off, cur);
    fill_kernel<<<(EE + 255) / 256, 256>>>(esrc, edst, cur, csr);
    wprep_kernel<<<(6 * 65536 + 255) / 256, 256>>>(Ws1, Ws2, wth, wtl);

    const int mtiles = (NN + 127) / 128;   // 391

    // ping-pong h buffers: x -> ha -> hb -> ha
    const float* hin = x;
    float* houts[LL] = {ha, hb, ha};
    for (int l = 0; l < LL; l++) {
        fused_layer_kernel<<<mtiles, 512, FUSED_SMEM>>>(
            hin, off, csr,
            wth + (size_t)l * 65536, wtl + (size_t)l * 65536, bs1 + l * DD,
            wth + (size_t)(3 + l) * 65536, wtl + (size_t)(3 + l) * 65536, bs2 + l * DD,
            houts[l], node_embed + (size_t)l * DD);
        hin = houts[l];
    }

    dim3 pgrid((NN + 127) / 128, LL);
    pool_kernel<<<pgrid, 256>>>(batch, node_embed, graph_embed);
    divide_kernel<<<(GG * ND + 255) / 256, 256>>>(graph_embed, counts);
}

// round 10
// speedup vs baseline: 1.0314x; 1.0088x over previous
#include <cuda_runtime.h>
#include <cuda_bf16.h>
#include <stdint.h>

#define NN 50000
#define EE 800000
#define DD 256
#define LL 3
#define GG 512
#define ND (LL * DD)   // 768

// ---------------------------------------------------------------------------
// Device scratch (ping-pong h buffers)
// ---------------------------------------------------------------------------
__device__ float g_ha[(size_t)NN * DD];
__device__ float g_hb[(size_t)NN * DD];
__device__ int   g_deg[NN];
__device__ int   g_off[NN + 1];
__device__ int   g_cur[NN];
__device__ int   g_csr[EE];
__device__ int   g_counts[GG];
__device__ __nv_bfloat16 g_wt_hi[6 * 256 * 256];
__device__ __nv_bfloat16 g_wt_lo[6 * 256 * 256];

// ---------------------------------------------------------------------------
// PTX helpers (sm_80-era only)
// ---------------------------------------------------------------------------
__device__ __forceinline__ uint32_t smem_u32(const void* p) {
    uint32_t a;
    asm("{ .reg .u64 t; cvta.to.shared.u64 t, %1; cvt.u32.u64 %0, t; }" : "=r"(a) : "l"(p));
    return a;
}
__device__ __forceinline__ void ldsm4(uint32_t* r, uint32_t addr) {
    asm volatile("ldmatrix.sync.aligned.m8n8.x4.shared.b16 {%0,%1,%2,%3}, [%4];"
        : "=r"(r[0]), "=r"(r[1]), "=r"(r[2]), "=r"(r[3]) : "r"(addr));
}
__device__ __forceinline__ void mma_bf16(float* d, const uint32_t* a, const uint32_t* b) {
    asm volatile("mma.sync.aligned.m16n8k16.row.col.f32.bf16.bf16.f32 "
        "{%0,%1,%2,%3}, {%4,%5,%6,%7}, {%8,%9}, {%0,%1,%2,%3};"
        : "+f"(d[0]), "+f"(d[1]), "+f"(d[2]), "+f"(d[3])
        : "r"(a[0]), "r"(a[1]), "r"(a[2]), "r"(a[3]), "r"(b[0]), "r"(b[1]));
}
#define CP_ASYNC16(dst, src) \
    asm volatile("cp.async.cg.shared.global [%0], [%1], 16;" :: "r"(dst), "l"(src) : "memory")
#define CP_COMMIT() asm volatile("cp.async.commit_group;" ::: "memory")
#define CP_WAIT1()  asm volatile("cp.async.wait_group 1;" ::: "memory")
#define CP_WAIT0()  asm volatile("cp.async.wait_group 0;" ::: "memory")

// ---------------------------------------------------------------------------
// Setup kernels (exactly 5 launches before the first fused kernel)
// ---------------------------------------------------------------------------
__global__ void init_zero_kernel(int* __restrict__ deg, int* __restrict__ counts,
                                 float* __restrict__ gev) {
    int i = blockIdx.x * blockDim.x + threadIdx.x;
    if (i < NN) deg[i] = 0;
    if (i < GG) counts[i] = 0;
    if (i < GG * ND) gev[i] = 0.0f;
}

__global__ void deg_count_kernel(const int* __restrict__ dst, const int* __restrict__ batch,
                                 int* __restrict__ deg, int* __restrict__ counts) {
    int i = blockIdx.x * blockDim.x + threadIdx.x;
    if (i < EE) atomicAdd(&deg[dst[i]], 1);
    if (i < NN) atomicAdd(&counts[batch[i]], 1);
}

__global__ void scan_kernel(const int* __restrict__ deg, int* __restrict__ off,
                            int* __restrict__ cur) {
    __shared__ int warp_sums[32];
    __shared__ int carry_s;
    const int tid = threadIdx.x;
    const int lane = tid & 31;
    const int wid = tid >> 5;
    if (tid == 0) carry_s = 0;
    __syncthreads();

    for (int base = 0; base < NN; base += 1024) {
        int i = base + tid;
        int v = (i < NN) ? deg[i] : 0;
        int incl = v;
#pragma unroll
        for (int o = 1; o < 32; o <<= 1) {
            int t = __shfl_up_sync(0xFFFFFFFFu, incl, o);
            if (lane >= o) incl += t;
        }
        if (lane == 31) warp_sums[wid] = incl;
        __syncthreads();
        if (wid == 0) {
            int ws = warp_sums[lane];
#pragma unroll
            for (int o = 1; o < 32; o <<= 1) {
                int t = __shfl_up_sync(0xFFFFFFFFu, ws, o);
                if (lane >= o) ws += t;
            }
            warp_sums[lane] = ws;
        }
        __syncthreads();
        int excl = incl - v + (wid > 0 ? warp_sums[wid - 1] : 0) + carry_s;
        if (i < NN) { off[i] = excl; cur[i] = excl; }
        __syncthreads();
        if (tid == 1023) carry_s = excl + v;
        __syncthreads();
    }
    if (tid == 0) off[NN] = carry_s;
}

__global__ void fill_kernel(const int* __restrict__ src, const int* __restrict__ dst,
                            int* __restrict__ cur, int* __restrict__ csr) {
    int e = blockIdx.x * blockDim.x + threadIdx.x;
    if (e >= EE) return;
    int d = dst[e];
    int p = atomicAdd(&cur[d], 1);
    csr[p] = src[e];
}

__global__ void wprep_kernel(const float* __restrict__ Ws1, const float* __restrict__ Ws2,
                             __nv_bfloat16* __restrict__ wh, __nv_bfloat16* __restrict__ wl) {
    int i = blockIdx.x * blockDim.x + threadIdx.x;
    if (i >= 6 * 65536) return;
    int mat = i >> 16;
    int rem = i & 65535;
    int k = rem >> 8, n = rem & 255;
    const float* W = (mat < 3) ? (Ws1 + (size_t)mat * 65536) : (Ws2 + (size_t)(mat - 3) * 65536);
    float x = W[k * 256 + n];
    __nv_bfloat16 hi = __float2bfloat16(x);
    __nv_bfloat16 lo = __float2bfloat16(x - __bfloat162float(hi));
    size_t o = ((size_t)mat << 16) + (size_t)n * 256 + k;
    wh[o] = hi;
    wl[o] = lo;
}

// ---------------------------------------------------------------------------
// Fused layer kernel: gather -> GEMM1 -> (t in smem) -> GEMM2 -> h + node_embed
// M-tile 64, 256 threads (8 warps), 2 CTAs/SM for cross-CTA phase overlap.
// smem: A/t tile hi/lo (64 x 528B x 2 = 67.6KB) + double-buffered W chunks
//       (KCH=16, swizzled 32B rows, 2 x 16KB) = 100.4KB total.
// ---------------------------------------------------------------------------
#define BM 64
#define AT_STR 528
#define OFF_ALO 33792              // 64*528
#define OFF_B 67584                // 2*33792
#define B_HALF 8192                // 256 rows * 32B
#define B_BUFSZ 16384
#define FUSED_SMEM 100352          // 67584 + 2*16384
#define NCHUNK 16                  // K/16

// B smem swizzle: row n, 16B-segment s (0/1): off = n*32 + ((s*16) ^ ((n&4)<<2))
__device__ __forceinline__ void issue_b_chunk(uint32_t sb,
        const __nv_bfloat16* __restrict__ Wh, const __nv_bfloat16* __restrict__ Wl,
        int kb, int buf, int tid) {
#pragma unroll
    for (int j = 0; j < 4; j++) {
        int i = tid + j * 256;            // 0..1023
        int half = i >> 9;
        int rem = i & 511;
        int n = rem >> 1;                 // 0..255
        int seg = rem & 1;                // 16B segment of 32B row
        const __nv_bfloat16* src = (half ? Wl : Wh) + (size_t)n * DD + kb + seg * 8;
        uint32_t dst = sb + OFF_B + (uint32_t)buf * B_BUFSZ + (uint32_t)half * B_HALF
                     + (uint32_t)n * 32 + (((uint32_t)seg * 16) ^ (((uint32_t)n & 4) << 2));
        CP_ASYNC16(dst, src);
    }
    CP_COMMIT();
}

__device__ __forceinline__ ushort2 split_hi(float a, float b) {
    ushort2 r;
    r.x = __bfloat16_as_ushort(__float2bfloat16(a));
    r.y = __bfloat16_as_ushort(__float2bfloat16(b));
    return r;
}
__device__ __forceinline__ ushort2 split_lo(float a, float b, ushort2 hi) {
    ushort2 r;
    r.x = __bfloat16_as_ushort(__float2bfloat16(a - __bfloat162float(__ushort_as_bfloat16(hi.x))));
    r.y = __bfloat16_as_ushort(__float2bfloat16(b - __bfloat162float(__ushort_as_bfloat16(hi.y))));
    return r;
}

template <bool TO_SMEM>
__device__ __forceinline__ void gemm_phase(char* smem, uint32_t sb,
        const __nv_bfloat16* __restrict__ Wh, const __nv_bfloat16* __restrict__ Wl,
        const float* __restrict__ bias, int bm,
        float* __restrict__ hout, float* __restrict__ ne) {
    const int tid = threadIdx.x;
    const int lane = tid & 31;
    const int w = tid >> 5;
    const int wm = (w & 1) * 32;          // 2 M-groups of 32
    const int wn = (w >> 1) * 64;         // 4 N-groups of 64
    const int frow = (lane & 7) + ((lane & 8) ? 8 : 0);
    const int fkc  = ((lane & 16) ? 8 : 0);
    const int brow = (lane & 7) + ((lane & 16) ? 8 : 0);
    const int bkc  = ((lane & 8) ? 8 : 0);

    float acc[2][8][4];
#pragma unroll
    for (int mi = 0; mi < 2; mi++)
#pragma unroll
        for (int nj = 0; nj < 8; nj++)
#pragma unroll
            for (int q = 0; q < 4; q++) acc[mi][nj][q] = 0.0f;

    for (int c = 0; c < NCHUNK; c++) {
        if (c < NCHUNK - 1) {
            issue_b_chunk(sb, Wh, Wl, (c + 1) * 16, (c + 1) & 1, tid);
            CP_WAIT1();
        } else {
            CP_WAIT0();
        }
        __syncthreads();

        const uint32_t bh_base = sb + OFF_B + (uint32_t)(c & 1) * B_BUFSZ;
        const uint32_t bl_base = bh_base + B_HALF;
        const int kA = c * 16;

        uint32_t ah[2][4], al[2][4];
#pragma unroll
        for (int mi = 0; mi < 2; mi++) {
            uint32_t o = (uint32_t)(wm + mi * 16 + frow) * AT_STR + (uint32_t)(kA + fkc) * 2;
            ldsm4(ah[mi], sb + o);
            ldsm4(al[mi], sb + OFF_ALO + o);
        }
#pragma unroll
        for (int p = 0; p < 4; p++) {
            const uint32_t nrow = (uint32_t)(wn + p * 16 + brow);
            const uint32_t o = nrow * 32 + (((uint32_t)bkc * 2) ^ ((nrow & 4) << 2));
            uint32_t th[4], tl[4];
            ldsm4(th, bh_base + o);
            ldsm4(tl, bl_base + o);
            uint32_t b0h[2] = {th[0], th[1]}, b1h[2] = {th[2], th[3]};
            uint32_t b0l[2] = {tl[0], tl[1]}, b1l[2] = {tl[2], tl[3]};
#pragma unroll
            for (int mi = 0; mi < 2; mi++) {
                mma_bf16(acc[mi][2 * p],     ah[mi], b0h);
                mma_bf16(acc[mi][2 * p],     ah[mi], b0l);
                mma_bf16(acc[mi][2 * p],     al[mi], b0h);
                mma_bf16(acc[mi][2 * p + 1], ah[mi], b1h);
                mma_bf16(acc[mi][2 * p + 1], ah[mi], b1l);
                mma_bf16(acc[mi][2 * p + 1], al[mi], b1h);
            }
        }
        __syncthreads();   // protect buffer reuse by next chunk's cp.async
    }

    // epilogue
    const int g2 = lane >> 2;
    const int tg2 = (lane & 3) * 2;
#pragma unroll
    for (int mi = 0; mi < 2; mi++) {
        const int r0l = wm + mi * 16 + g2;
        const int r1l = r0l + 8;
#pragma unroll
        for (int nj = 0; nj < 8; nj++) {
            const int col = wn + nj * 8 + tg2;
            float b0 = __ldg(&bias[col]);
            float b1 = __ldg(&bias[col + 1]);
            float v00 = fmaxf(acc[mi][nj][0] + b0, 0.0f);
            float v01 = fmaxf(acc[mi][nj][1] + b1, 0.0f);
            float v10 = fmaxf(acc[mi][nj][2] + b0, 0.0f);
            float v11 = fmaxf(acc[mi][nj][3] + b1, 0.0f);
            if (TO_SMEM) {
                uint32_t o0 = (uint32_t)r0l * AT_STR + (uint32_t)col * 2;
                uint32_t o1 = (uint32_t)r1l * AT_STR + (uint32_t)col * 2;
                ushort2 h0 = split_hi(v00, v01);
                ushort2 h1 = split_hi(v10, v11);
                *(ushort2*)(smem + o0) = h0;
                *(ushort2*)(smem + o1) = h1;
                *(ushort2*)(smem + OFF_ALO + o0) = split_lo(v00, v01, h0);
                *(ushort2*)(smem + OFF_ALO + o1) = split_lo(v10, v11, h1);
            } else {
                const int r0 = bm + r0l, r1 = bm + r1l;
                if (r0 < NN) {
                    float2 v = make_float2(v00, v01);
                    *(float2*)(hout + (size_t)r0 * DD + col) = v;
                    *(float2*)(ne + (size_t)r0 * ND + col) = v;
                }
                if (r1 < NN) {
                    float2 v = make_float2(v10, v11);
                    *(float2*)(hout + (size_t)r1 * DD + col) = v;
                    *(float2*)(ne + (size_t)r1 * ND + col) = v;
                }
            }
        }
    }
}

__global__ __launch_bounds__(256, 2)
void fused_layer_kernel(const float* __restrict__ hin,
                        const int* __restrict__ off, const int* __restrict__ csr,
                        const __nv_bfloat16* __restrict__ W1h, const __nv_bfloat16* __restrict__ W1l,
                        const float* __restrict__ b1,
                        const __nv_bfloat16* __restrict__ W2h, const __nv_bfloat16* __restrict__ W2l,
                        const float* __restrict__ b2,
                        float* __restrict__ hout, float* __restrict__ ne) {
    extern __shared__ char smem[];
    const uint32_t sb = smem_u32(smem);
    const int tid = threadIdx.x;
    const int lane = tid & 31;
    const int w = tid >> 5;
    const int bm = blockIdx.x * BM;

    // start W1 chunk0 early (overlaps with gather)
    issue_b_chunk(sb, W1h, W1l, 0, 0, tid);

    // gather: warp-per-row; coalesced CSR index fetch + shfl broadcast
    const float4* __restrict__ h4 = (const float4*)hin;
#pragma unroll 1
    for (int rr = 0; rr < 8; rr++) {
        const int rl = w * 8 + rr;
        const int gr = bm + rl;
        float4 a0 = make_float4(0.f, 0.f, 0.f, 0.f);
        float4 a1 = make_float4(0.f, 0.f, 0.f, 0.f);
        if (gr < NN) {
            a0 = __ldg(&h4[(size_t)gr * 64 + lane]);
            a1 = __ldg(&h4[(size_t)gr * 64 + lane + 32]);
            int j = __ldg(&off[gr]);
            const int je = __ldg(&off[gr + 1]);
            while (j < je) {
                const int cnt = min(32, je - j);
                int myidx = (lane < cnt) ? __ldg(&csr[j + lane]) : 0;
                int e = 0;
                for (; e + 4 <= cnt; e += 4) {
                    int s0 = __shfl_sync(0xFFFFFFFFu, myidx, e);
                    int s1 = __shfl_sync(0xFFFFFFFFu, myidx, e + 1);
                    int s2 = __shfl_sync(0xFFFFFFFFu, myidx, e + 2);
                    int s3 = __shfl_sync(0xFFFFFFFFu, myidx, e + 3);
                    float4 v0 = __ldg(&h4[(size_t)s0 * 64 + lane]);
                    float4 u0 = __ldg(&h4[(size_t)s0 * 64 + lane + 32]);
                    float4 v1 = __ldg(&h4[(size_t)s1 * 64 + lane]);
                    float4 u1 = __ldg(&h4[(size_t)s1 * 64 + lane + 32]);
                    float4 v2 = __ldg(&h4[(size_t)s2 * 64 + lane]);
                    float4 u2 = __ldg(&h4[(size_t)s2 * 64 + lane + 32]);
                    float4 v3 = __ldg(&h4[(size_t)s3 * 64 + lane]);
                    float4 u3 = __ldg(&h4[(size_t)s3 * 64 + lane + 32]);
                    a0.x += v0.x + v1.x; a0.y += v0.y + v1.y;
                    a0.z += v0.z + v1.z; a0.w += v0.w + v1.w;
                    a0.x += v2.x + v3.x; a0.y += v2.y + v3.y;
                    a0.z += v2.z + v3.z; a0.w += v2.w + v3.w;
                    a1.x += u0.x + u1.x; a1.y += u0.y + u1.y;
                    a1.z += u0.z + u1.z; a1.w += u0.w + u1.w;
                    a1.x += u2.x + u3.x; a1.y += u2.y + u3.y;
                    a1.z += u2.z + u3.z; a1.w += u2.w + u3.w;
                }
                for (; e < cnt; e++) {
                    int s0 = __shfl_sync(0xFFFFFFFFu, myidx, e);
                    float4 v0 = __ldg(&h4[(size_t)s0 * 64 + lane]);
                    float4 u0 = __ldg(&h4[(size_t)s0 * 64 + lane + 32]);
                    a0.x += v0.x; a0.y += v0.y; a0.z += v0.z; a0.w += v0.w;
                    a1.x += u0.x; a1.y += u0.y; a1.z += u0.z; a1.w += u0.w;
                }
                j += cnt;
            }
        }
        // bf16 hi/lo split + store into A tile
        char* base = smem + (uint32_t)rl * AT_STR + (uint32_t)lane * 8;
        ushort2 h0a = split_hi(a0.x, a0.y);
        ushort2 h0b = split_hi(a0.z, a0.w);
        ushort4 hh0; hh0.x = h0a.x; hh0.y = h0a.y; hh0.z = h0b.x; hh0.w = h0b.y;
        ushort2 l0a = split_lo(a0.x, a0.y, h0a);
        ushort2 l0b = split_lo(a0.z, a0.w, h0b);
        ushort4 ll0; ll0.x = l0a.x; ll0.y = l0a.y; ll0.z = l0b.x; ll0.w = l0b.y;
        *(ushort4*)(base) = hh0;
        *(ushort4*)(base + OFF_ALO) = ll0;
        ushort2 h1a = split_hi(a1.x, a1.y);
        ushort2 h1b = split_hi(a1.z, a1.w);
        ushort4 hh1; hh1.x = h1a.x; hh1.y = h1a.y; hh1.z = h1b.x; hh1.w = h1b.y;
        ushort2 l1a = split_lo(a1.x, a1.y, h1a);
        ushort2 l1b = split_lo(a1.z, a1.w, h1b);
        ushort4 ll1; ll1.x = l1a.x; ll1.y = l1a.y; ll1.z = l1b.x; ll1.w = l1b.y;
        *(ushort4*)(base + 256) = hh1;
        *(ushort4*)(base + OFF_ALO + 256) = ll1;
    }
    __syncthreads();

    // phase 1: t = relu(agg @ W1 + b1) -> smem (overwrites A tile)
    gemm_phase<true>(smem, sb, W1h, W1l, b1, bm, nullptr, nullptr);
    __syncthreads();

    // phase 2: h = relu(t @ W2 + b2) -> gmem
    issue_b_chunk(sb, W2h, W2l, 0, 0, tid);
    gemm_phase<false>(smem, sb, W2h, W2l, b2, bm, hout, ne);
}

// ---------------------------------------------------------------------------
// Pooling with run compression (batch sorted)
// ---------------------------------------------------------------------------
__global__ __launch_bounds__(256)
void pool_kernel(const int* __restrict__ batch, const float* __restrict__ ne,
                 float* __restrict__ gev) {
    const int c = blockIdx.y * 256 + threadIdx.x;
    const int n0 = blockIdx.x * 128;
    int n1 = n0 + 128; if (n1 > NN) n1 = NN;

    int g = __ldg(&batch[n0]);
    float acc = 0.0f;
    for (int n = n0; n < n1; n++) {
        int gn = __ldg(&batch[n]);
        if (gn != g) {
            atomicAdd(&gev[(size_t)g * ND + c], acc);
            acc = 0.0f;
            g = gn;
        }
        acc += __ldg(&ne[(size_t)n * ND + c]);
    }
    atomicAdd(&gev[(size_t)g * ND + c], acc);
}

__global__ void divide_kernel(float* __restrict__ gev, const int* __restrict__ counts) {
    int i = blockIdx.x * blockDim.x + threadIdx.x;
    if (i >= GG * ND) return;
    int g = i / ND;
    int cnt = counts[g];
    gev[i] *= 1.0f / (float)(cnt > 0 ? cnt : 1);
}

// ---------------------------------------------------------------------------
// Launch
// ---------------------------------------------------------------------------
extern "C" void kernel_launch(void* const* d_in, const int* in_sizes, int n_in,
                              void* d_out, int out_size) {
    const float* x          = (const float*)d_in[0];
    const int*   edge_index = (const int*)d_in[1];
    const int*   batch      = (const int*)d_in[2];
    const float* Ws1        = (const float*)d_in[3];
    const float* bs1        = (const float*)d_in[4];
    const float* Ws2        = (const float*)d_in[5];
    const float* bs2        = (const float*)d_in[6];

    float* out = (float*)d_out;
    float* graph_embed = out;
    float* node_embed  = out + (size_t)GG * ND;

    float* ha;   cudaGetSymbolAddress((void**)&ha,   g_ha);
    float* hb;   cudaGetSymbolAddress((void**)&hb,   g_hb);
    int* deg;    cudaGetSymbolAddress((void**)&deg,  g_deg);
    int* off;    cudaGetSymbolAddress((void**)&off,  g_off);
    int* cur;    cudaGetSymbolAddress((void**)&cur,  g_cur);
    int* csr;    cudaGetSymbolAddress((void**)&csr,  g_csr);
    int* counts; cudaGetSymbolAddress((void**)&counts, g_counts);
    __nv_bfloat16* wth; cudaGetSymbolAddress((void**)&wth, g_wt_hi);
    __nv_bfloat16* wtl; cudaGetSymbolAddress((void**)&wtl, g_wt_lo);

    cudaFuncSetAttribute(fused_layer_kernel, cudaFuncAttributeMaxDynamicSharedMemorySize, FUSED_SMEM);

    const int* esrc = edge_index;
    const int* edst = edge_index + EE;

    // ---- exactly 5 setup launches (ncu -s 5 -c 1 captures fused kernel) ----
    init_zero_kernel<<<(GG * ND + 255) / 256, 256>>>(deg, counts, graph_embed);
    deg_count_kernel<<<(EE + 255) / 256, 256>>>(edst, batch, deg, counts);
    scan_kernel<<<1, 1024>>>(deg, off, cur);
    fill_kernel<<<(EE + 255) / 256, 256>>>(esrc, edst, cur, csr);
    wprep_kernel<<<(6 * 65536 + 255) / 256, 256>>>(Ws1, Ws2, wth, wtl);

    const int mtiles = (NN + BM - 1) / BM;   // 782

    // ping-pong h buffers: x -> ha -> hb -> ha
    const float* hin = x;
    float* houts[LL] = {ha, hb, ha};
    for (int l = 0; l < LL; l++) {
        fused_layer_kernel<<<mtiles, 256, FUSED_SMEM>>>(
            hin, off, csr,
            wth + (size_t)l * 65536, wtl + (size_t)l * 65536, bs1 + l * DD,
            wth + (size_t)(3 + l) * 65536, wtl + (size_t)(3 + l) * 65536, bs2 + l * DD,
            houts[l], node_embed + (size_t)l * DD);
        hin = houts[l];
    }

    dim3 pgrid((NN + 127) / 128, LL);
    pool_kernel<<<pgrid, 256>>>(batch, node_embed, graph_embed);
    divide_kernel<<<(GG * ND + 255) / 256, 256>>>(graph_embed, counts);
}

// round 11
// speedup vs baseline: 1.3839x; 1.3418x over previous
#include <cuda_runtime.h>
#include <cuda_bf16.h>
#include <cuda_fp16.h>
#include <stdint.h>

#define NN 50000
#define EE 800000
#define DD 256
#define LL 3
#define GG 512
#define ND (LL * DD)   // 768

// ---------------------------------------------------------------------------
// Device scratch (ping-pong h buffers)
// ---------------------------------------------------------------------------
__device__ float g_ha[(size_t)NN * DD];
__device__ float g_hb[(size_t)NN * DD];
__device__ int   g_deg[NN];
__device__ int   g_off[NN + 1];
__device__ int   g_cur[NN];
__device__ int   g_csr[EE];
__device__ int   g_counts[GG];
__device__ __half g_wt[6 * 256 * 256];   // fp16-rounded W, transposed [N][K]

// ---------------------------------------------------------------------------
// PTX helpers (sm_80-era only)
// ---------------------------------------------------------------------------
__device__ __forceinline__ uint32_t smem_u32(const void* p) {
    uint32_t a;
    asm("{ .reg .u64 t; cvta.to.shared.u64 t, %1; cvt.u32.u64 %0, t; }" : "=r"(a) : "l"(p));
    return a;
}
__device__ __forceinline__ void ldsm4(uint32_t* r, uint32_t addr) {
    asm volatile("ldmatrix.sync.aligned.m8n8.x4.shared.b16 {%0,%1,%2,%3}, [%4];"
        : "=r"(r[0]), "=r"(r[1]), "=r"(r[2]), "=r"(r[3]) : "r"(addr));
}
__device__ __forceinline__ void mma_f16(float* d, const uint32_t* a, const uint32_t* b) {
    asm volatile("mma.sync.aligned.m16n8k16.row.col.f32.f16.f16.f32 "
        "{%0,%1,%2,%3}, {%4,%5,%6,%7}, {%8,%9}, {%0,%1,%2,%3};"
        : "+f"(d[0]), "+f"(d[1]), "+f"(d[2]), "+f"(d[3])
        : "r"(a[0]), "r"(a[1]), "r"(a[2]), "r"(a[3]), "r"(b[0]), "r"(b[1]));
}
#define CP_ASYNC16(dst, src) \
    asm volatile("cp.async.cg.shared.global [%0], [%1], 16;" :: "r"(dst), "l"(src) : "memory")
#define CP_COMMIT() asm volatile("cp.async.commit_group;" ::: "memory")
#define CP_WAIT1()  asm volatile("cp.async.wait_group 1;" ::: "memory")
#define CP_WAIT0()  asm volatile("cp.async.wait_group 0;" ::: "memory")

// ---------------------------------------------------------------------------
// Setup kernels (5 launches before the first fused kernel)
// ---------------------------------------------------------------------------
__global__ void init_zero_kernel(int* __restrict__ deg, int* __restrict__ counts,
                                 float* __restrict__ gev) {
    int i = blockIdx.x * blockDim.x + threadIdx.x;
    if (i < NN) deg[i] = 0;
    if (i < GG) counts[i] = 0;
    if (i < GG * ND) gev[i] = 0.0f;
}

__global__ void deg_count_kernel(const int* __restrict__ dst, const int* __restrict__ batch,
                                 int* __restrict__ deg, int* __restrict__ counts) {
    int i = blockIdx.x * blockDim.x + threadIdx.x;
    if (i < EE) atomicAdd(&deg[dst[i]], 1);
    if (i < NN) atomicAdd(&counts[batch[i]], 1);
}

__global__ void scan_kernel(const int* __restrict__ deg, int* __restrict__ off,
                            int* __restrict__ cur) {
    __shared__ int warp_sums[32];
    __shared__ int carry_s;
    const int tid = threadIdx.x;
    const int lane = tid & 31;
    const int wid = tid >> 5;
    if (tid == 0) carry_s = 0;
    __syncthreads();

    for (int base = 0; base < NN; base += 1024) {
        int i = base + tid;
        int v = (i < NN) ? deg[i] : 0;
        int incl = v;
#pragma unroll
        for (int o = 1; o < 32; o <<= 1) {
            int t = __shfl_up_sync(0xFFFFFFFFu, incl, o);
            if (lane >= o) incl += t;
        }
        if (lane == 31) warp_sums[wid] = incl;
        __syncthreads();
        if (wid == 0) {
            int ws = warp_sums[lane];
#pragma unroll
            for (int o = 1; o < 32; o <<= 1) {
                int t = __shfl_up_sync(0xFFFFFFFFu, ws, o);
                if (lane >= o) ws += t;
            }
            warp_sums[lane] = ws;
        }
        __syncthreads();
        int excl = incl - v + (wid > 0 ? warp_sums[wid - 1] : 0) + carry_s;
        if (i < NN) { off[i] = excl; cur[i] = excl; }
        __syncthreads();
        if (tid == 1023) carry_s = excl + v;
        __syncthreads();
    }
    if (tid == 0) off[NN] = carry_s;
}

__global__ void fill_kernel(const int* __restrict__ src, const int* __restrict__ dst,
                            int* __restrict__ cur, int* __restrict__ csr) {
    int e = blockIdx.x * blockDim.x + threadIdx.x;
    if (e >= EE) return;
    int d = dst[e];
    int p = atomicAdd(&cur[d], 1);
    csr[p] = src[e];
}

// transpose + fp16 round of the 6 weight matrices; output [N][K] row-major
__global__ void wprep_kernel(const float* __restrict__ Ws1, const float* __restrict__ Ws2,
                             __half* __restrict__ wh) {
    int i = blockIdx.x * blockDim.x + threadIdx.x;
    if (i >= 6 * 65536) return;
    int mat = i >> 16;
    int rem = i & 65535;
    int k = rem >> 8, n = rem & 255;
    const float* W = (mat < 3) ? (Ws1 + (size_t)mat * 65536) : (Ws2 + (size_t)(mat - 3) * 65536);
    float x = W[k * 256 + n];
    wh[((size_t)mat << 16) + (size_t)n * 256 + k] = __float2half_rn(x);
}

// ---------------------------------------------------------------------------
// Fused layer kernel: gather -> GEMM1 -> (t in smem) -> GEMM2 -> h + node_embed
// M-tile 64, 256 threads (8 warps), 2 CTAs/SM.
// fp16x2 scheme: A split hi/lo fp16; W rounded to fp16 once. 2 mma passes.
// smem: A/t tile hi/lo (64 x 528B x 2 = 67.6KB) + double-buffered W chunks
//       (KCH=16, swizzled 32B rows, 2 x 8KB) = 84KB total.
// ---------------------------------------------------------------------------
#define BM 64
#define AT_STR 528
#define OFF_ALO 33792              // 64*528
#define OFF_B 67584                // 2*33792
#define B_BUFSZ 8192               // 256 rows * 32B
#define FUSED_SMEM 83968           // 67584 + 2*8192
#define NCHUNK 16                  // K/16

// B smem swizzle: row n, 16B-segment s (0/1): off = n*32 + ((s*16) ^ ((n&4)<<2))
__device__ __forceinline__ void issue_b_chunk(uint32_t sb,
        const __half* __restrict__ Wh, int kb, int buf, int tid) {
#pragma unroll
    for (int j = 0; j < 2; j++) {
        int i = tid + j * 256;            // 0..511
        int n = i >> 1;                   // 0..255
        int seg = i & 1;                  // 16B segment of 32B row
        const __half* src = Wh + (size_t)n * DD + kb + seg * 8;
        uint32_t dst = sb + OFF_B + (uint32_t)buf * B_BUFSZ
                     + (uint32_t)n * 32 + (((uint32_t)seg * 16) ^ (((uint32_t)n & 4) << 2));
        CP_ASYNC16(dst, src);
    }
    CP_COMMIT();
}

__device__ __forceinline__ ushort2 split_hi(float a, float b) {
    ushort2 r;
    r.x = __half_as_ushort(__float2half_rn(a));
    r.y = __half_as_ushort(__float2half_rn(b));
    return r;
}
__device__ __forceinline__ ushort2 split_lo(float a, float b, ushort2 hi) {
    ushort2 r;
    r.x = __half_as_ushort(__float2half_rn(a - __half2float(__ushort_as_half(hi.x))));
    r.y = __half_as_ushort(__float2half_rn(b - __half2float(__ushort_as_half(hi.y))));
    return r;
}

template <bool TO_SMEM>
__device__ __forceinline__ void gemm_phase(char* smem, uint32_t sb,
        const __half* __restrict__ Wh,
        const float* __restrict__ bias, int bm,
        float* __restrict__ hout, float* __restrict__ ne) {
    const int tid = threadIdx.x;
    const int lane = tid & 31;
    const int w = tid >> 5;
    const int wm = (w & 1) * 32;          // 2 M-groups of 32
    const int wn = (w >> 1) * 64;         // 4 N-groups of 64
    const int frow = (lane & 7) + ((lane & 8) ? 8 : 0);
    const int fkc  = ((lane & 16) ? 8 : 0);
    const int brow = (lane & 7) + ((lane & 16) ? 8 : 0);
    const int bkc  = ((lane & 8) ? 8 : 0);

    float acc[2][8][4];
#pragma unroll
    for (int mi = 0; mi < 2; mi++)
#pragma unroll
        for (int nj = 0; nj < 8; nj++)
#pragma unroll
            for (int q = 0; q < 4; q++) acc[mi][nj][q] = 0.0f;

    for (int c = 0; c < NCHUNK; c++) {
        if (c < NCHUNK - 1) {
            issue_b_chunk(sb, Wh, (c + 1) * 16, (c + 1) & 1, tid);
            CP_WAIT1();
        } else {
            CP_WAIT0();
        }
        __syncthreads();

        const uint32_t bh_base = sb + OFF_B + (uint32_t)(c & 1) * B_BUFSZ;
        const int kA = c * 16;

        uint32_t ah[2][4], al[2][4];
#pragma unroll
        for (int mi = 0; mi < 2; mi++) {
            uint32_t o = (uint32_t)(wm + mi * 16 + frow) * AT_STR + (uint32_t)(kA + fkc) * 2;
            ldsm4(ah[mi], sb + o);
            ldsm4(al[mi], sb + OFF_ALO + o);
        }
#pragma unroll
        for (int p = 0; p < 4; p++) {
            const uint32_t nrow = (uint32_t)(wn + p * 16 + brow);
            const uint32_t o = nrow * 32 + (((uint32_t)bkc * 2) ^ ((nrow & 4) << 2));
            uint32_t th[4];
            ldsm4(th, bh_base + o);
            uint32_t b0h[2] = {th[0], th[1]}, b1h[2] = {th[2], th[3]};
#pragma unroll
            for (int mi = 0; mi < 2; mi++) {
                mma_f16(acc[mi][2 * p],     ah[mi], b0h);
                mma_f16(acc[mi][2 * p],     al[mi], b0h);
                mma_f16(acc[mi][2 * p + 1], ah[mi], b1h);
                mma_f16(acc[mi][2 * p + 1], al[mi], b1h);
            }
        }
        __syncthreads();   // protect buffer reuse by next chunk's cp.async
    }

    // epilogue
    const int g2 = lane >> 2;
    const int tg2 = (lane & 3) * 2;
#pragma unroll
    for (int mi = 0; mi < 2; mi++) {
        const int r0l = wm + mi * 16 + g2;
        const int r1l = r0l + 8;
#pragma unroll
        for (int nj = 0; nj < 8; nj++) {
            const int col = wn + nj * 8 + tg2;
            float b0 = __ldg(&bias[col]);
            float b1 = __ldg(&bias[col + 1]);
            float v00 = fmaxf(acc[mi][nj][0] + b0, 0.0f);
            float v01 = fmaxf(acc[mi][nj][1] + b1, 0.0f);
            float v10 = fmaxf(acc[mi][nj][2] + b0, 0.0f);
            float v11 = fmaxf(acc[mi][nj][3] + b1, 0.0f);
            if (TO_SMEM) {
                uint32_t o0 = (uint32_t)r0l * AT_STR + (uint32_t)col * 2;
                uint32_t o1 = (uint32_t)r1l * AT_STR + (uint32_t)col * 2;
                ushort2 h0 = split_hi(v00, v01);
                ushort2 h1 = split_hi(v10, v11);
                *(ushort2*)(smem + o0) = h0;
                *(ushort2*)(smem + o1) = h1;
                *(ushort2*)(smem + OFF_ALO + o0) = split_lo(v00, v01, h0);
                *(ushort2*)(smem + OFF_ALO + o1) = split_lo(v10, v11, h1);
            } else {
                const int r0 = bm + r0l, r1 = bm + r1l;
                if (r0 < NN) {
                    float2 v = make_float2(v00, v01);
                    *(float2*)(hout + (size_t)r0 * DD + col) = v;
                    *(float2*)(ne + (size_t)r0 * ND + col) = v;
                }
                if (r1 < NN) {
                    float2 v = make_float2(v10, v11);
                    *(float2*)(hout + (size_t)r1 * DD + col) = v;
                    *(float2*)(ne + (size_t)r1 * ND + col) = v;
                }
            }
        }
    }
}

__global__ __launch_bounds__(256, 2)
void fused_layer_kernel(const float* __restrict__ hin,
                        const int* __restrict__ off, const int* __restrict__ csr,
                        const __half* __restrict__ W1h, const float* __restrict__ b1,
                        const __half* __restrict__ W2h, const float* __restrict__ b2,
                        float* __restrict__ hout, float* __restrict__ ne) {
    extern __shared__ char smem[];
    const uint32_t sb = smem_u32(smem);
    const int tid = threadIdx.x;
    const int lane = tid & 31;
    const int w = tid >> 5;
    const int bm = blockIdx.x * BM;

    // start W1 chunk0 early (overlaps with gather)
    issue_b_chunk(sb, W1h, 0, 0, tid);

    // gather: warp-per-row; coalesced CSR index fetch + shfl broadcast
    const float4* __restrict__ h4 = (const float4*)hin;
#pragma unroll 1
    for (int rr = 0; rr < 8; rr++) {
        const int rl = w * 8 + rr;
        const int gr = bm + rl;
        float4 a0 = make_float4(0.f, 0.f, 0.f, 0.f);
        float4 a1 = make_float4(0.f, 0.f, 0.f, 0.f);
        if (gr < NN) {
            a0 = __ldg(&h4[(size_t)gr * 64 + lane]);
            a1 = __ldg(&h4[(size_t)gr * 64 + lane + 32]);
            int j = __ldg(&off[gr]);
            const int je = __ldg(&off[gr + 1]);
            while (j < je) {
                const int cnt = min(32, je - j);
                int myidx = (lane < cnt) ? __ldg(&csr[j + lane]) : 0;
                int e = 0;
                for (; e + 4 <= cnt; e += 4) {
                    int s0 = __shfl_sync(0xFFFFFFFFu, myidx, e);
                    int s1 = __shfl_sync(0xFFFFFFFFu, myidx, e + 1);
                    int s2 = __shfl_sync(0xFFFFFFFFu, myidx, e + 2);
                    int s3 = __shfl_sync(0xFFFFFFFFu, myidx, e + 3);
                    float4 v0 = __ldg(&h4[(size_t)s0 * 64 + lane]);
                    float4 u0 = __ldg(&h4[(size_t)s0 * 64 + lane + 32]);
                    float4 v1 = __ldg(&h4[(size_t)s1 * 64 + lane]);
                    float4 u1 = __ldg(&h4[(size_t)s1 * 64 + lane + 32]);
                    float4 v2 = __ldg(&h4[(size_t)s2 * 64 + lane]);
                    float4 u2 = __ldg(&h4[(size_t)s2 * 64 + lane + 32]);
                    float4 v3 = __ldg(&h4[(size_t)s3 * 64 + lane]);
                    float4 u3 = __ldg(&h4[(size_t)s3 * 64 + lane + 32]);
                    a0.x += v0.x + v1.x; a0.y += v0.y + v1.y;
                    a0.z += v0.z + v1.z; a0.w += v0.w + v1.w;
                    a0.x += v2.x + v3.x; a0.y += v2.y + v3.y;
                    a0.z += v2.z + v3.z; a0.w += v2.w + v3.w;
                    a1.x += u0.x + u1.x; a1.y += u0.y + u1.y;
                    a1.z += u0.z + u1.z; a1.w += u0.w + u1.w;
                    a1.x += u2.x + u3.x; a1.y += u2.y + u3.y;
                    a1.z += u2.z + u3.z; a1.w += u2.w + u3.w;
                }
                for (; e < cnt; e++) {
                    int s0 = __shfl_sync(0xFFFFFFFFu, myidx, e);
                    float4 v0 = __ldg(&h4[(size_t)s0 * 64 + lane]);
                    float4 u0 = __ldg(&h4[(size_t)s0 * 64 + lane + 32]);
                    a0.x += v0.x; a0.y += v0.y; a0.z += v0.z; a0.w += v0.w;
                    a1.x += u0.x; a1.y += u0.y; a1.z += u0.z; a1.w += u0.w;
                }
                j += cnt;
            }
        }
        // fp16 hi/lo split + store into A tile
        char* base = smem + (uint32_t)rl * AT_STR + (uint32_t)lane * 8;
        ushort2 h0a = split_hi(a0.x, a0.y);
        ushort2 h0b = split_hi(a0.z, a0.w);
        ushort4 hh0; hh0.x = h0a.x; hh0.y = h0a.y; hh0.z = h0b.x; hh0.w = h0b.y;
        ushort2 l0a = split_lo(a0.x, a0.y, h0a);
        ushort2 l0b = split_lo(a0.z, a0.w, h0b);
        ushort4 ll0; ll0.x = l0a.x; ll0.y = l0a.y; ll0.z = l0b.x; ll0.w = l0b.y;
        *(ushort4*)(base) = hh0;
        *(ushort4*)(base + OFF_ALO) = ll0;
        ushort2 h1a = split_hi(a1.x, a1.y);
        ushort2 h1b = split_hi(a1.z, a1.w);
        ushort4 hh1; hh1.x = h1a.x; hh1.y = h1a.y; hh1.z = h1b.x; hh1.w = h1b.y;
        ushort2 l1a = split_lo(a1.x, a1.y, h1a);
        ushort2 l1b = split_lo(a1.z, a1.w, h1b);
        ushort4 ll1; ll1.x = l1a.x; ll1.y = l1a.y; ll1.z = l1b.x; ll1.w = l1b.y;
        *(ushort4*)(base + 256) = hh1;
        *(ushort4*)(base + OFF_ALO + 256) = ll1;
    }
    __syncthreads();

    // phase 1: t = relu(agg @ W1 + b1) -> smem (overwrites A tile)
    gemm_phase<true>(smem, sb, W1h, b1, bm, nullptr, nullptr);
    __syncthreads();

    // phase 2: h = relu(t @ W2 + b2) -> gmem
    issue_b_chunk(sb, W2h, 0, 0, tid);
    gemm_phase<false>(smem, sb, W2h, b2, bm, hout, ne);
}

// ---------------------------------------------------------------------------
// Pooling with run compression (batch sorted)
// ---------------------------------------------------------------------------
__global__ __launch_bounds__(256)
void pool_kernel(const int* __restrict__ batch, const float* __restrict__ ne,
                 float* __restrict__ gev) {
    const int c = blockIdx.y * 256 + threadIdx.x;
    const int n0 = blockIdx.x * 128;
    int n1 = n0 + 128; if (n1 > NN) n1 = NN;

    int g = __ldg(&batch[n0]);
    float acc = 0.0f;
    for (int n = n0; n < n1; n++) {
        int gn = __ldg(&batch[n]);
        if (gn != g) {
            atomicAdd(&gev[(size_t)g * ND + c], acc);
            acc = 0.0f;
            g = gn;
        }
        acc += __ldg(&ne[(size_t)n * ND + c]);
    }
    atomicAdd(&gev[(size_t)g * ND + c], acc);
}

__global__ void divide_kernel(float* __restrict__ gev, const int* __restrict__ counts) {
    int i = blockIdx.x * blockDim.x + threadIdx.x;
    if (i >= GG * ND) return;
    int g = i / ND;
    int cnt = counts[g];
    gev[i] *= 1.0f / (float)(cnt > 0 ? cnt : 1);
}

// ---------------------------------------------------------------------------
// Launch
// ---------------------------------------------------------------------------
extern "C" void kernel_launch(void* const* d_in, const int* in_sizes, int n_in,
                              void* d_out, int out_size) {
    const float* x          = (const float*)d_in[0];
    const int*   edge_index = (const int*)d_in[1];
    const int*   batch      = (const int*)d_in[2];
    const float* Ws1        = (const float*)d_in[3];
    const float* bs1        = (const float*)d_in[4];
    const float* Ws2        = (const float*)d_in[5];
    const float* bs2        = (const float*)d_in[6];

    float* out = (float*)d_out;
    float* graph_embed = out;
    float* node_embed  = out + (size_t)GG * ND;

    float* ha;   cudaGetSymbolAddress((void**)&ha,   g_ha);
    float* hb;   cudaGetSymbolAddress((void**)&hb,   g_hb);
    int* deg;    cudaGetSymbolAddress((void**)&deg,  g_deg);
    int* off;    cudaGetSymbolAddress((void**)&off,  g_off);
    int* cur;    cudaGetSymbolAddress((void**)&cur,  g_cur);
    int* csr;    cudaGetSymbolAddress((void**)&csr,  g_csr);
    int* counts; cudaGetSymbolAddress((void**)&counts, g_counts);
    __half* wt;  cudaGetSymbolAddress((void**)&wt,   g_wt);

    cudaFuncSetAttribute(fused_layer_kernel, cudaFuncAttributeMaxDynamicSharedMemorySize, FUSED_SMEM);

    const int* esrc = edge_index;
    const int* edst = edge_index + EE;

    // ---- setup launches ----
    init_zero_kernel<<<(GG * ND + 255) / 256, 256>>>(deg, counts, graph_embed);
    deg_count_kernel<<<(EE + 255) / 256, 256>>>(edst, batch, deg, counts);
    scan_kernel<<<1, 1024>>>(deg, off, cur);
    fill_kernel<<<(EE + 255) / 256, 256>>>(esrc, edst, cur, csr);
    wprep_kernel<<<(6 * 65536 + 255) / 256, 256>>>(Ws1, Ws2, wt);

    const int mtiles = (NN + BM - 1) / BM;   // 782

    // ping-pong h buffers: x -> ha -> hb -> ha
    const float* hin = x;
    float* houts[LL] = {ha, hb, ha};
    for (int l = 0; l < LL; l++) {
        fused_layer_kernel<<<mtiles, 256, FUSED_SMEM>>>(
            hin, off, csr,
            wt + (size_t)l * 65536, bs1 + l * DD,
            wt + (size_t)(3 + l) * 65536, bs2 + l * DD,
            houts[l], node_embed + (size_t)l * DD);
        hin = houts[l];
    }

    dim3 pgrid((NN + 127) / 128, LL);
    pool_kernel<<<pgrid, 256>>>(batch, node_embed, graph_embed);
    divide_kernel<<<(GG * ND + 255) / 256, 256>>>(graph_embed, counts);
}

// round 12
// speedup vs baseline: 1.4494x; 1.0473x over previous
#include <cuda_runtime.h>
#include <cuda_bf16.h>
#include <cuda_fp16.h>
#include <stdint.h>

#define NN 50000
#define EE 800000
#define DD 256
#define LL 3
#define GG 512
#define ND (LL * DD)   // 768

// ---------------------------------------------------------------------------
// Device scratch
// ---------------------------------------------------------------------------
__device__ __half g_x16[(size_t)NN * DD];
__device__ __half g_ha[(size_t)NN * DD];
__device__ __half g_hb[(size_t)NN * DD];
__device__ int    g_deg[NN];
__device__ int    g_off[NN + 1];
__device__ int    g_cur[NN];
__device__ int    g_csr[EE];
__device__ int    g_counts[GG];
__device__ __half g_wt[6 * 256 * 256];   // fp16-rounded W, transposed [N][K]

// ---------------------------------------------------------------------------
// PTX helpers (sm_80-era only)
// ---------------------------------------------------------------------------
__device__ __forceinline__ uint32_t smem_u32(const void* p) {
    uint32_t a;
    asm("{ .reg .u64 t; cvta.to.shared.u64 t, %1; cvt.u32.u64 %0, t; }" : "=r"(a) : "l"(p));
    return a;
}
__device__ __forceinline__ void ldsm4(uint32_t* r, uint32_t addr) {
    asm volatile("ldmatrix.sync.aligned.m8n8.x4.shared.b16 {%0,%1,%2,%3}, [%4];"
        : "=r"(r[0]), "=r"(r[1]), "=r"(r[2]), "=r"(r[3]) : "r"(addr));
}
__device__ __forceinline__ void mma_f16(float* d, const uint32_t* a, const uint32_t* b) {
    asm volatile("mma.sync.aligned.m16n8k16.row.col.f32.f16.f16.f32 "
        "{%0,%1,%2,%3}, {%4,%5,%6,%7}, {%8,%9}, {%0,%1,%2,%3};"
        : "+f"(d[0]), "+f"(d[1]), "+f"(d[2]), "+f"(d[3])
        : "r"(a[0]), "r"(a[1]), "r"(a[2]), "r"(a[3]), "r"(b[0]), "r"(b[1]));
}
#define CP_ASYNC16(dst, src) \
    asm volatile("cp.async.cg.shared.global [%0], [%1], 16;" :: "r"(dst), "l"(src) : "memory")
#define CP_COMMIT() asm volatile("cp.async.commit_group;" ::: "memory")
#define CP_WAIT1()  asm volatile("cp.async.wait_group 1;" ::: "memory")
#define CP_WAIT0()  asm volatile("cp.async.wait_group 0;" ::: "memory")

// ---------------------------------------------------------------------------
// Setup kernels
// ---------------------------------------------------------------------------
__global__ void init_zero_kernel(int* __restrict__ deg, int* __restrict__ counts,
                                 float* __restrict__ gev) {
    int i = blockIdx.x * blockDim.x + threadIdx.x;
    if (i < NN) deg[i] = 0;
    if (i < GG) counts[i] = 0;
    if (i < GG * ND) gev[i] = 0.0f;
}

__global__ void deg_count_kernel(const int* __restrict__ dst, const int* __restrict__ batch,
                                 int* __restrict__ deg, int* __restrict__ counts) {
    int i = blockIdx.x * blockDim.x + threadIdx.x;
    if (i < EE) atomicAdd(&deg[dst[i]], 1);
    if (i < NN) atomicAdd(&counts[batch[i]], 1);
}

__global__ void scan_kernel(const int* __restrict__ deg, int* __restrict__ off,
                            int* __restrict__ cur) {
    __shared__ int warp_sums[32];
    __shared__ int carry_s;
    const int tid = threadIdx.x;
    const int lane = tid & 31;
    const int wid = tid >> 5;
    if (tid == 0) carry_s = 0;
    __syncthreads();

    for (int base = 0; base < NN; base += 1024) {
        int i = base + tid;
        int v = (i < NN) ? deg[i] : 0;
        int incl = v;
#pragma unroll
        for (int o = 1; o < 32; o <<= 1) {
            int t = __shfl_up_sync(0xFFFFFFFFu, incl, o);
            if (lane >= o) incl += t;
        }
        if (lane == 31) warp_sums[wid] = incl;
        __syncthreads();
        if (wid == 0) {
            int ws = warp_sums[lane];
#pragma unroll
            for (int o = 1; o < 32; o <<= 1) {
                int t = __shfl_up_sync(0xFFFFFFFFu, ws, o);
                if (lane >= o) ws += t;
            }
            warp_sums[lane] = ws;
        }
        __syncthreads();
        int excl = incl - v + (wid > 0 ? warp_sums[wid - 1] : 0) + carry_s;
        if (i < NN) { off[i] = excl; cur[i] = excl; }
        __syncthreads();
        if (tid == 1023) carry_s = excl + v;
        __syncthreads();
    }
    if (tid == 0) off[NN] = carry_s;
}

__global__ void fill_kernel(const int* __restrict__ src, const int* __restrict__ dst,
                            int* __restrict__ cur, int* __restrict__ csr) {
    int e = blockIdx.x * blockDim.x + threadIdx.x;
    if (e >= EE) return;
    int d = dst[e];
    int p = atomicAdd(&cur[d], 1);
    csr[p] = src[e];
}

// transpose + fp16 round of the 6 weight matrices; output [N][K] row-major
__global__ void wprep_kernel(const float* __restrict__ Ws1, const float* __restrict__ Ws2,
                             __half* __restrict__ wh) {
    int i = blockIdx.x * blockDim.x + threadIdx.x;
    if (i >= 6 * 65536) return;
    int mat = i >> 16;
    int rem = i & 65535;
    int k = rem >> 8, n = rem & 255;
    const float* W = (mat < 3) ? (Ws1 + (size_t)mat * 65536) : (Ws2 + (size_t)(mat - 3) * 65536);
    float x = W[k * 256 + n];
    wh[((size_t)mat << 16) + (size_t)n * 256 + k] = __float2half_rn(x);
}

// x -> fp16 (one time)
__global__ void xcvt_kernel(const float* __restrict__ x, __half* __restrict__ x16) {
    int i = blockIdx.x * blockDim.x + threadIdx.x;
    if (i >= NN * DD / 4) return;
    float4 v = __ldg((const float4*)x + i);
    __half2 a = __floats2half2_rn(v.x, v.y);
    __half2 b = __floats2half2_rn(v.z, v.w);
    uint2 o;
    o.x = *(uint32_t*)&a;
    o.y = *(uint32_t*)&b;
    *((uint2*)x16 + i) = o;
}

// ---------------------------------------------------------------------------
// Fused layer kernel: gather -> GEMM1 -> (t in smem) -> GEMM2 -> h + node_embed
// M-tile 64, 256 threads (8 warps), 2 CTAs/SM.
// h stored fp16 (gather traffic halved); fp16x2 GEMM (A hi/lo, W fp16, 2 passes).
// ---------------------------------------------------------------------------
#define BM 64
#define AT_STR 528
#define OFF_ALO 33792              // 64*528
#define OFF_B 67584                // 2*33792
#define B_BUFSZ 8192               // 256 rows * 32B
#define FUSED_SMEM 83968           // 67584 + 2*8192
#define NCHUNK 16                  // K/16

// B smem swizzle: row n, 16B-segment s (0/1): off = n*32 + ((s*16) ^ ((n&4)<<2))
__device__ __forceinline__ void issue_b_chunk(uint32_t sb,
        const __half* __restrict__ Wh, int kb, int buf, int tid) {
#pragma unroll
    for (int j = 0; j < 2; j++) {
        int i = tid + j * 256;            // 0..511
        int n = i >> 1;                   // 0..255
        int seg = i & 1;                  // 16B segment of 32B row
        const __half* src = Wh + (size_t)n * DD + kb + seg * 8;
        uint32_t dst = sb + OFF_B + (uint32_t)buf * B_BUFSZ
                     + (uint32_t)n * 32 + (((uint32_t)seg * 16) ^ (((uint32_t)n & 4) << 2));
        CP_ASYNC16(dst, src);
    }
    CP_COMMIT();
}

__device__ __forceinline__ ushort2 split_hi(float a, float b) {
    ushort2 r;
    r.x = __half_as_ushort(__float2half_rn(a));
    r.y = __half_as_ushort(__float2half_rn(b));
    return r;
}
__device__ __forceinline__ ushort2 split_lo(float a, float b, ushort2 hi) {
    ushort2 r;
    r.x = __half_as_ushort(__float2half_rn(a - __half2float(__ushort_as_half(hi.x))));
    r.y = __half_as_ushort(__float2half_rn(b - __half2float(__ushort_as_half(hi.y))));
    return r;
}

__device__ __forceinline__ void acc_u4(float* acc, uint4 v) {
    float2 f0 = __half22float2(*(__half2*)&v.x);
    float2 f1 = __half22float2(*(__half2*)&v.y);
    float2 f2 = __half22float2(*(__half2*)&v.z);
    float2 f3 = __half22float2(*(__half2*)&v.w);
    acc[0] += f0.x; acc[1] += f0.y; acc[2] += f1.x; acc[3] += f1.y;
    acc[4] += f2.x; acc[5] += f2.y; acc[6] += f3.x; acc[7] += f3.y;
}

template <bool TO_SMEM>
__device__ __forceinline__ void gemm_phase(char* smem, uint32_t sb,
        const __half* __restrict__ Wh,
        const float* __restrict__ bias, int bm,
        __half* __restrict__ hout, float* __restrict__ ne) {
    const int tid = threadIdx.x;
    const int lane = tid & 31;
    const int w = tid >> 5;
    const int wm = (w & 1) * 32;          // 2 M-groups of 32
    const int wn = (w >> 1) * 64;         // 4 N-groups of 64
    const int frow = (lane & 7) + ((lane & 8) ? 8 : 0);
    const int fkc  = ((lane & 16) ? 8 : 0);
    const int brow = (lane & 7) + ((lane & 16) ? 8 : 0);
    const int bkc  = ((lane & 8) ? 8 : 0);

    float acc[2][8][4];
#pragma unroll
    for (int mi = 0; mi < 2; mi++)
#pragma unroll
        for (int nj = 0; nj < 8; nj++)
#pragma unroll
            for (int q = 0; q < 4; q++) acc[mi][nj][q] = 0.0f;

    for (int c = 0; c < NCHUNK; c++) {
        if (c < NCHUNK - 1) {
            issue_b_chunk(sb, Wh, (c + 1) * 16, (c + 1) & 1, tid);
            CP_WAIT1();
        } else {
            CP_WAIT0();
        }
        __syncthreads();

        const uint32_t bh_base = sb + OFF_B + (uint32_t)(c & 1) * B_BUFSZ;
        const int kA = c * 16;

        uint32_t ah[2][4], al[2][4];
#pragma unroll
        for (int mi = 0; mi < 2; mi++) {
            uint32_t o = (uint32_t)(wm + mi * 16 + frow) * AT_STR + (uint32_t)(kA + fkc) * 2;
            ldsm4(ah[mi], sb + o);
            ldsm4(al[mi], sb + OFF_ALO + o);
        }
#pragma unroll
        for (int p = 0; p < 4; p++) {
            const uint32_t nrow = (uint32_t)(wn + p * 16 + brow);
            const uint32_t o = nrow * 32 + (((uint32_t)bkc * 2) ^ ((nrow & 4) << 2));
            uint32_t th[4];
            ldsm4(th, bh_base + o);
            uint32_t b0h[2] = {th[0], th[1]}, b1h[2] = {th[2], th[3]};
#pragma unroll
            for (int mi = 0; mi < 2; mi++) {
                mma_f16(acc[mi][2 * p],     ah[mi], b0h);
                mma_f16(acc[mi][2 * p],     al[mi], b0h);
                mma_f16(acc[mi][2 * p + 1], ah[mi], b1h);
                mma_f16(acc[mi][2 * p + 1], al[mi], b1h);
            }
        }
        __syncthreads();   // protect buffer reuse by next chunk's cp.async
    }

    // epilogue
    const int g2 = lane >> 2;
    const int tg2 = (lane & 3) * 2;
#pragma unroll
    for (int mi = 0; mi < 2; mi++) {
        const int r0l = wm + mi * 16 + g2;
        const int r1l = r0l + 8;
#pragma unroll
        for (int nj = 0; nj < 8; nj++) {
            const int col = wn + nj * 8 + tg2;
            float b0 = __ldg(&bias[col]);
            float b1 = __ldg(&bias[col + 1]);
            float v00 = fmaxf(acc[mi][nj][0] + b0, 0.0f);
            float v01 = fmaxf(acc[mi][nj][1] + b1, 0.0f);
            float v10 = fmaxf(acc[mi][nj][2] + b0, 0.0f);
            float v11 = fmaxf(acc[mi][nj][3] + b1, 0.0f);
            if (TO_SMEM) {
                uint32_t o0 = (uint32_t)r0l * AT_STR + (uint32_t)col * 2;
                uint32_t o1 = (uint32_t)r1l * AT_STR + (uint32_t)col * 2;
                ushort2 h0 = split_hi(v00, v01);
                ushort2 h1 = split_hi(v10, v11);
                *(ushort2*)(smem + o0) = h0;
                *(ushort2*)(smem + o1) = h1;
                *(ushort2*)(smem + OFF_ALO + o0) = split_lo(v00, v01, h0);
                *(ushort2*)(smem + OFF_ALO + o1) = split_lo(v10, v11, h1);
            } else {
                const int r0 = bm + r0l, r1 = bm + r1l;
                if (r0 < NN) {
                    __half2 hv = __floats2half2_rn(v00, v01);
                    *(__half2*)(hout + (size_t)r0 * DD + col) = hv;
                    *(float2*)(ne + (size_t)r0 * ND + col) = make_float2(v00, v01);
                }
                if (r1 < NN) {
                    __half2 hv = __floats2half2_rn(v10, v11);
                    *(__half2*)(hout + (size_t)r1 * DD + col) = hv;
                    *(float2*)(ne + (size_t)r1 * ND + col) = make_float2(v10, v11);
                }
            }
        }
    }
}

__global__ __launch_bounds__(256, 2)
void fused_layer_kernel(const __half* __restrict__ hin,
                        const int* __restrict__ off, const int* __restrict__ csr,
                        const __half* __restrict__ W1h, const float* __restrict__ b1,
                        const __half* __restrict__ W2h, const float* __restrict__ b2,
                        __half* __restrict__ hout, float* __restrict__ ne) {
    extern __shared__ char smem[];
    const uint32_t sb = smem_u32(smem);
    const int tid = threadIdx.x;
    const int lane = tid & 31;
    const int w = tid >> 5;
    const int bm = blockIdx.x * BM;

    // start W1 chunk0 early (overlaps with gather)
    issue_b_chunk(sb, W1h, 0, 0, tid);

    // gather: warp-per-row; h rows are fp16 (512B) -> one uint4 per lane per row.
    const uint4* __restrict__ h16 = (const uint4*)hin;   // 32 uint4 per row
#pragma unroll 1
    for (int rr = 0; rr < 8; rr++) {
        const int rl = w * 8 + rr;
        const int gr = bm + rl;
        float acc[8];
#pragma unroll
        for (int q = 0; q < 8; q++) acc[q] = 0.0f;
        if (gr < NN) {
            acc_u4(acc, __ldg(&h16[(size_t)gr * 32 + lane]));
            int j = __ldg(&off[gr]);
            const int je = __ldg(&off[gr + 1]);
            while (j < je) {
                const int cnt = min(32, je - j);
                int myidx = (lane < cnt) ? __ldg(&csr[j + lane]) : 0;
                int e = 0;
                for (; e + 4 <= cnt; e += 4) {
                    int s0 = __shfl_sync(0xFFFFFFFFu, myidx, e);
                    int s1 = __shfl_sync(0xFFFFFFFFu, myidx, e + 1);
                    int s2 = __shfl_sync(0xFFFFFFFFu, myidx, e + 2);
                    int s3 = __shfl_sync(0xFFFFFFFFu, myidx, e + 3);
                    uint4 v0 = __ldg(&h16[(size_t)s0 * 32 + lane]);
                    uint4 v1 = __ldg(&h16[(size_t)s1 * 32 + lane]);
                    uint4 v2 = __ldg(&h16[(size_t)s2 * 32 + lane]);
                    uint4 v3 = __ldg(&h16[(size_t)s3 * 32 + lane]);
                    acc_u4(acc, v0);
                    acc_u4(acc, v1);
                    acc_u4(acc, v2);
                    acc_u4(acc, v3);
                }
                for (; e < cnt; e++) {
                    int s0 = __shfl_sync(0xFFFFFFFFu, myidx, e);
                    acc_u4(acc, __ldg(&h16[(size_t)s0 * 32 + lane]));
                }
                j += cnt;
            }
        }
        // fp16 hi/lo split; lane owns cols [8*lane, 8*lane+8)
        char* base = smem + (uint32_t)rl * AT_STR + (uint32_t)lane * 16;
        ushort2 h0 = split_hi(acc[0], acc[1]);
        ushort2 h1 = split_hi(acc[2], acc[3]);
        ushort2 h2 = split_hi(acc[4], acc[5]);
        ushort2 h3 = split_hi(acc[6], acc[7]);
        ushort2 l0 = split_lo(acc[0], acc[1], h0);
        ushort2 l1 = split_lo(acc[2], acc[3], h1);
        ushort2 l2 = split_lo(acc[4], acc[5], h2);
        ushort2 l3 = split_lo(acc[6], acc[7], h3);
        uint4 hv, lv;
        hv.x = (uint32_t)h0.x | ((uint32_t)h0.y << 16);
        hv.y = (uint32_t)h1.x | ((uint32_t)h1.y << 16);
        hv.z = (uint32_t)h2.x | ((uint32_t)h2.y << 16);
        hv.w = (uint32_t)h3.x | ((uint32_t)h3.y << 16);
        lv.x = (uint32_t)l0.x | ((uint32_t)l0.y << 16);
        lv.y = (uint32_t)l1.x | ((uint32_t)l1.y << 16);
        lv.z = (uint32_t)l2.x | ((uint32_t)l2.y << 16);
        lv.w = (uint32_t)l3.x | ((uint32_t)l3.y << 16);
        *(uint4*)(base) = hv;
        *(uint4*)(base + OFF_ALO) = lv;
    }
    __syncthreads();

    // phase 1: t = relu(agg @ W1 + b1) -> smem (overwrites A tile)
    gemm_phase<true>(smem, sb, W1h, b1, bm, nullptr, nullptr);
    __syncthreads();

    // phase 2: h = relu(t @ W2 + b2) -> gmem (fp16 hout + fp32 node_embed)
    issue_b_chunk(sb, W2h, 0, 0, tid);
    gemm_phase<false>(smem, sb, W2h, b2, bm, hout, ne);
}

// ---------------------------------------------------------------------------
// Pooling with run compression (batch sorted)
// ---------------------------------------------------------------------------
__global__ __launch_bounds__(256)
void pool_kernel(const int* __restrict__ batch, const float* __restrict__ ne,
                 float* __restrict__ gev) {
    const int c = blockIdx.y * 256 + threadIdx.x;
    const int n0 = blockIdx.x * 128;
    int n1 = n0 + 128; if (n1 > NN) n1 = NN;

    int g = __ldg(&batch[n0]);
    float acc = 0.0f;
    for (int n = n0; n < n1; n++) {
        int gn = __ldg(&batch[n]);
        if (gn != g) {
            atomicAdd(&gev[(size_t)g * ND + c], acc);
            acc = 0.0f;
            g = gn;
        }
        acc += __ldg(&ne[(size_t)n * ND + c]);
    }
    atomicAdd(&gev[(size_t)g * ND + c], acc);
}

__global__ void divide_kernel(float* __restrict__ gev, const int* __restrict__ counts) {
    int i = blockIdx.x * blockDim.x + threadIdx.x;
    if (i >= GG * ND) return;
    int g = i / ND;
    int cnt = counts[g];
    gev[i] *= 1.0f / (float)(cnt > 0 ? cnt : 1);
}

// ---------------------------------------------------------------------------
// Launch
// ---------------------------------------------------------------------------
extern "C" void kernel_launch(void* const* d_in, const int* in_sizes, int n_in,
                              void* d_out, int out_size) {
    const float* x          = (const float*)d_in[0];
    const int*   edge_index = (const int*)d_in[1];
    const int*   batch      = (const int*)d_in[2];
    const float* Ws1        = (const float*)d_in[3];
    const float* bs1        = (const float*)d_in[4];
    const float* Ws2        = (const float*)d_in[5];
    const float* bs2        = (const float*)d_in[6];

    float* out = (float*)d_out;
    float* graph_embed = out;
    float* node_embed  = out + (size_t)GG * ND;

    __half* x16; cudaGetSymbolAddress((void**)&x16, g_x16);
    __half* ha;  cudaGetSymbolAddress((void**)&ha,  g_ha);
    __half* hb;  cudaGetSymbolAddress((void**)&hb,  g_hb);
    int* deg;    cudaGetSymbolAddress((void**)&deg, g_deg);
    int* off;    cudaGetSymbolAddress((void**)&off, g_off);
    int* cur;    cudaGetSymbolAddress((void**)&cur, g_cur);
    int* csr;    cudaGetSymbolAddress((void**)&csr, g_csr);
    int* counts; cudaGetSymbolAddress((void**)&counts, g_counts);
    __half* wt;  cudaGetSymbolAddress((void**)&wt,  g_wt);

    cudaFuncSetAttribute(fused_layer_kernel, cudaFuncAttributeMaxDynamicSharedMemorySize, FUSED_SMEM);

    const int* esrc = edge_index;
    const int* edst = edge_index + EE;

    // ---- setup launches ----
    init_zero_kernel<<<(GG * ND + 255) / 256, 256>>>(deg, counts, graph_embed);
    deg_count_kernel<<<(EE + 255) / 256, 256>>>(edst, batch, deg, counts);
    scan_kernel<<<1, 1024>>>(deg, off, cur);
    fill_kernel<<<(EE + 255) / 256, 256>>>(esrc, edst, cur, csr);
    wprep_kernel<<<(6 * 65536 + 255) / 256, 256>>>(Ws1, Ws2, wt);
    xcvt_kernel<<<(NN * DD / 4 + 255) / 256, 256>>>(x, x16);

    const int mtiles = (NN + BM - 1) / BM;   // 782

    // ping-pong h buffers: x16 -> ha -> hb -> ha
    const __half* hin = x16;
    __half* houts[LL] = {ha, hb, ha};
    for (int l = 0; l < LL; l++) {
        fused_layer_kernel<<<mtiles, 256, FUSED_SMEM>>>(
            hin, off, csr,
            wt + (size_t)l * 65536, bs1 + l * DD,
            wt + (size_t)(3 + l) * 65536, bs2 + l * DD,
            houts[l], node_embed + (size_t)l * DD);
        hin = houts[l];
    }

    dim3 pgrid((NN + 127) / 128, LL);
    pool_kernel<<<pgrid, 256>>>(batch, node_embed, graph_embed);
    divide_kernel<<<(GG * ND + 255) / 256, 256>>>(graph_embed, counts);
}

// round 16
// speedup vs baseline: 1.6588x; 1.1445x over previous
#include <cuda_runtime.h>
#include <cuda_bf16.h>
#include <cuda_fp16.h>
#include <stdint.h>

#define NN 50000
#define EE 800000
#define DD 256
#define LL 3
#define GG 512
#define ND (LL * DD)   // 768

// ---------------------------------------------------------------------------
// Device scratch: three persistent fp16 layer buffers (also pooled from)
// ---------------------------------------------------------------------------
__device__ __half g_x16[(size_t)NN * DD];
__device__ __half g_ha[(size_t)NN * DD];
__device__ __half g_hb[(size_t)NN * DD];
__device__ __half g_hc[(size_t)NN * DD];
__device__ int    g_deg[NN];
__device__ int    g_off[NN + 1];
__device__ int    g_cur[NN];
__device__ int    g_csr[EE];
__device__ int    g_counts[GG];
__device__ __half g_wt[6 * 256 * 256];   // fp16-rounded W, transposed [N][K]

// ---------------------------------------------------------------------------
// PTX helpers (sm_80-era only)
// ---------------------------------------------------------------------------
__device__ __forceinline__ uint32_t smem_u32(const void* p) {
    uint32_t a;
    asm("{ .reg .u64 t; cvta.to.shared.u64 t, %1; cvt.u32.u64 %0, t; }" : "=r"(a) : "l"(p));
    return a;
}
__device__ __forceinline__ void ldsm4(uint32_t* r, uint32_t addr) {
    asm volatile("ldmatrix.sync.aligned.m8n8.x4.shared.b16 {%0,%1,%2,%3}, [%4];"
        : "=r"(r[0]), "=r"(r[1]), "=r"(r[2]), "=r"(r[3]) : "r"(addr));
}
__device__ __forceinline__ void mma_f16(float* d, const uint32_t* a, const uint32_t* b) {
    asm volatile("mma.sync.aligned.m16n8k16.row.col.f32.f16.f16.f32 "
        "{%0,%1,%2,%3}, {%4,%5,%6,%7}, {%8,%9}, {%0,%1,%2,%3};"
        : "+f"(d[0]), "+f"(d[1]), "+f"(d[2]), "+f"(d[3])
        : "r"(a[0]), "r"(a[1]), "r"(a[2]), "r"(a[3]), "r"(b[0]), "r"(b[1]));
}
#define CP_ASYNC16(dst, src) \
    asm volatile("cp.async.cg.shared.global [%0], [%1], 16;" :: "r"(dst), "l"(src) : "memory")
#define CP_COMMIT() asm volatile("cp.async.commit_group;" ::: "memory")
#define CP_WAIT1()  asm volatile("cp.async.wait_group 1;" ::: "memory")
#define CP_WAIT0()  asm volatile("cp.async.wait_group 0;" ::: "memory")

// ---------------------------------------------------------------------------
// Setup kernels
// ---------------------------------------------------------------------------
__global__ void init_zero_kernel(int* __restrict__ deg, int* __restrict__ counts,
                                 float* __restrict__ gev) {
    int i = blockIdx.x * blockDim.x + threadIdx.x;
    if (i < NN) deg[i] = 0;
    if (i < GG) counts[i] = 0;
    if (i < GG * ND) gev[i] = 0.0f;
}

__global__ void deg_count_kernel(const int* __restrict__ dst, const int* __restrict__ batch,
                                 int* __restrict__ deg, int* __restrict__ counts) {
    int i = blockIdx.x * blockDim.x + threadIdx.x;
    if (i < EE) atomicAdd(&deg[dst[i]], 1);
    if (i < NN) atomicAdd(&counts[batch[i]], 1);
}

__global__ void scan_kernel(const int* __restrict__ deg, int* __restrict__ off,
                            int* __restrict__ cur) {
    __shared__ int warp_sums[32];
    __shared__ int carry_s;
    const int tid = threadIdx.x;
    const int lane = tid & 31;
    const int wid = tid >> 5;
    if (tid == 0) carry_s = 0;
    __syncthreads();

    for (int base = 0; base < NN; base += 1024) {
        int i = base + tid;
        int v = (i < NN) ? deg[i] : 0;
        int incl = v;
#pragma unroll
        for (int o = 1; o < 32; o <<= 1) {
            int t = __shfl_up_sync(0xFFFFFFFFu, incl, o);
            if (lane >= o) incl += t;
        }
        if (lane == 31) warp_sums[wid] = incl;
        __syncthreads();
        if (wid == 0) {
            int ws = warp_sums[lane];
#pragma unroll
            for (int o = 1; o < 32; o <<= 1) {
                int t = __shfl_up_sync(0xFFFFFFFFu, ws, o);
                if (lane >= o) ws += t;
            }
            warp_sums[lane] = ws;
        }
        __syncthreads();
        int excl = incl - v + (wid > 0 ? warp_sums[wid - 1] : 0) + carry_s;
        if (i < NN) { off[i] = excl; cur[i] = excl; }
        __syncthreads();
        if (tid == 1023) carry_s = excl + v;
        __syncthreads();
    }
    if (tid == 0) off[NN] = carry_s;
}

__global__ void fill_kernel(const int* __restrict__ src, const int* __restrict__ dst,
                            int* __restrict__ cur, int* __restrict__ csr) {
    int e = blockIdx.x * blockDim.x + threadIdx.x;
    if (e >= EE) return;
    int d = dst[e];
    int p = atomicAdd(&cur[d], 1);
    csr[p] = src[e];
}

// transpose + fp16 round of the 6 weight matrices; output [N][K] row-major
__global__ void wprep_kernel(const float* __restrict__ Ws1, const float* __restrict__ Ws2,
                             __half* __restrict__ wh) {
    int i = blockIdx.x * blockDim.x + threadIdx.x;
    if (i >= 6 * 65536) return;
    int mat = i >> 16;
    int rem = i & 65535;
    int k = rem >> 8, n = rem & 255;
    const float* W = (mat < 3) ? (Ws1 + (size_t)mat * 65536) : (Ws2 + (size_t)(mat - 3) * 65536);
    float x = W[k * 256 + n];
    wh[((size_t)mat << 16) + (size_t)n * 256 + k] = __float2half_rn(x);
}

// x -> fp16 (one time)
__global__ void xcvt_kernel(const float* __restrict__ x, __half* __restrict__ x16) {
    int i = blockIdx.x * blockDim.x + threadIdx.x;
    if (i >= NN * DD / 4) return;
    float4 v = __ldg((const float4*)x + i);
    __half2 a = __floats2half2_rn(v.x, v.y);
    __half2 b = __floats2half2_rn(v.z, v.w);
    uint2 o;
    o.x = *(uint32_t*)&a;
    o.y = *(uint32_t*)&b;
    *((uint2*)x16 + i) = o;
}

// ---------------------------------------------------------------------------
// Fused layer kernel: gather -> GEMM1 -> (t in smem) -> GEMM2 -> h + node_embed
// M-tile 64, 256 threads (8 warps), 2 CTAs/SM.
// Single-pass fp16 MMA (A rounded to fp16, W rounded to fp16).
// smem: A/t tile fp16 (64 x 528B = 33.8KB) + double-buffered W (2 x 8KB) = 50KB
// ---------------------------------------------------------------------------
#define BM 64
#define AT_STR 528
#define OFF_B 33792                // 64*528
#define B_BUFSZ 8192               // 256 rows * 32B
#define FUSED_SMEM 50176           // 33792 + 2*8192
#define NCHUNK 16                  // K/16

// B smem swizzle: row n, 16B-segment s (0/1): off = n*32 + ((s*16) ^ ((n&4)<<2))
__device__ __forceinline__ void issue_b_chunk(uint32_t sb,
        const __half* __restrict__ Wh, int kb, int buf, int tid) {
#pragma unroll
    for (int j = 0; j < 2; j++) {
        int i = tid + j * 256;            // 0..511
        int n = i >> 1;                   // 0..255
        int seg = i & 1;                  // 16B segment of 32B row
        const __half* src = Wh + (size_t)n * DD + kb + seg * 8;
        uint32_t dst = sb + OFF_B + (uint32_t)buf * B_BUFSZ
                     + (uint32_t)n * 32 + (((uint32_t)seg * 16) ^ (((uint32_t)n & 4) << 2));
        CP_ASYNC16(dst, src);
    }
    CP_COMMIT();
}

__device__ __forceinline__ ushort2 pack_h2(float a, float b) {
    ushort2 r;
    r.x = __half_as_ushort(__float2half_rn(a));
    r.y = __half_as_ushort(__float2half_rn(b));
    return r;
}

__device__ __forceinline__ void acc_u4(float* acc, uint4 v) {
    float2 f0 = __half22float2(*(__half2*)&v.x);
    float2 f1 = __half22float2(*(__half2*)&v.y);
    float2 f2 = __half22float2(*(__half2*)&v.z);
    float2 f3 = __half22float2(*(__half2*)&v.w);
    acc[0] += f0.x; acc[1] += f0.y; acc[2] += f1.x; acc[3] += f1.y;
    acc[4] += f2.x; acc[5] += f2.y; acc[6] += f3.x; acc[7] += f3.y;
}

template <bool TO_SMEM>
__device__ __forceinline__ void gemm_phase(char* smem, uint32_t sb,
        const __half* __restrict__ Wh,
        const float* __restrict__ bias, int bm,
        __half* __restrict__ hout, float* __restrict__ ne) {
    const int tid = threadIdx.x;
    const int lane = tid & 31;
    const int w = tid >> 5;
    const int wm = (w & 1) * 32;          // 2 M-groups of 32
    const int wn = (w >> 1) * 64;         // 4 N-groups of 64
    const int frow = (lane & 7) + ((lane & 8) ? 8 : 0);
    const int fkc  = ((lane & 16) ? 8 : 0);
    const int brow = (lane & 7) + ((lane & 16) ? 8 : 0);
    const int bkc  = ((lane & 8) ? 8 : 0);

    float acc[2][8][4];
#pragma unroll
    for (int mi = 0; mi < 2; mi++)
#pragma unroll
        for (int nj = 0; nj < 8; nj++)
#pragma unroll
            for (int q = 0; q < 4; q++) acc[mi][nj][q] = 0.0f;

    for (int c = 0; c < NCHUNK; c++) {
        if (c < NCHUNK - 1) {
            issue_b_chunk(sb, Wh, (c + 1) * 16, (c + 1) & 1, tid);
            CP_WAIT1();
        } else {
            CP_WAIT0();
        }
        __syncthreads();

        const uint32_t bh_base = sb + OFF_B + (uint32_t)(c & 1) * B_BUFSZ;
        const int kA = c * 16;

        uint32_t ah[2][4];
#pragma unroll
        for (int mi = 0; mi < 2; mi++) {
            uint32_t o = (uint32_t)(wm + mi * 16 + frow) * AT_STR + (uint32_t)(kA + fkc) * 2;
            ldsm4(ah[mi], sb + o);
        }
#pragma unroll
        for (int p = 0; p < 4; p++) {
            const uint32_t nrow = (uint32_t)(wn + p * 16 + brow);
            const uint32_t o = nrow * 32 + (((uint32_t)bkc * 2) ^ ((nrow & 4) << 2));
            uint32_t th[4];
            ldsm4(th, bh_base + o);
            uint32_t b0h[2] = {th[0], th[1]}, b1h[2] = {th[2], th[3]};
#pragma unroll
            for (int mi = 0; mi < 2; mi++) {
                mma_f16(acc[mi][2 * p],     ah[mi], b0h);
                mma_f16(acc[mi][2 * p + 1], ah[mi], b1h);
            }
        }
        __syncthreads();   // protect buffer reuse by next chunk's cp.async
    }

    // epilogue
    const int g2 = lane >> 2;
    const int tg2 = (lane & 3) * 2;
#pragma unroll
    for (int mi = 0; mi < 2; mi++) {
        const int r0l = wm + mi * 16 + g2;
        const int r1l = r0l + 8;
#pragma unroll
        for (int nj = 0; nj < 8; nj++) {
            const int col = wn + nj * 8 + tg2;
            float b0 = __ldg(&bias[col]);
            float b1 = __ldg(&bias[col + 1]);
            float v00 = fmaxf(acc[mi][nj][0] + b0, 0.0f);
            float v01 = fmaxf(acc[mi][nj][1] + b1, 0.0f);
            float v10 = fmaxf(acc[mi][nj][2] + b0, 0.0f);
            float v11 = fmaxf(acc[mi][nj][3] + b1, 0.0f);
            if (TO_SMEM) {
                uint32_t o0 = (uint32_t)r0l * AT_STR + (uint32_t)col * 2;
                uint32_t o1 = (uint32_t)r1l * AT_STR + (uint32_t)col * 2;
                *(ushort2*)(smem + o0) = pack_h2(v00, v01);
                *(ushort2*)(smem + o1) = pack_h2(v10, v11);
            } else {
                const int r0 = bm + r0l, r1 = bm + r1l;
                if (r0 < NN) {
                    ushort2 hv = pack_h2(v00, v01);
                    *(ushort2*)(hout + (size_t)r0 * DD + col) = hv;
                    *(float2*)(ne + (size_t)r0 * ND + col) = make_float2(v00, v01);
                }
                if (r1 < NN) {
                    ushort2 hv = pack_h2(v10, v11);
                    *(ushort2*)(hout + (size_t)r1 * DD + col) = hv;
                    *(float2*)(ne + (size_t)r1 * ND + col) = make_float2(v10, v11);
                }
            }
        }
    }
}

__global__ __launch_bounds__(256, 2)
void fused_layer_kernel(const __half* __restrict__ hin,
                        const int* __restrict__ off, const int* __restrict__ csr,
                        const __half* __restrict__ W1h, const float* __restrict__ b1,
                        const __half* __restrict__ W2h, const float* __restrict__ b2,
                        __half* __restrict__ hout, float* __restrict__ ne) {
    extern __shared__ char smem[];
    const uint32_t sb = smem_u32(smem);
    const int tid = threadIdx.x;
    const int lane = tid & 31;
    const int w = tid >> 5;
    const int bm = blockIdx.x * BM;

    // start W1 chunk0 early (overlaps with gather)
    issue_b_chunk(sb, W1h, 0, 0, tid);

    // gather: warp-per-row; fp16 rows (512B) -> one uint4 per lane per row.
    const uint4* __restrict__ h16 = (const uint4*)hin;   // 32 uint4 per row
#pragma unroll 1
    for (int rr = 0; rr < 8; rr++) {
        const int rl = w * 8 + rr;
        const int gr = bm + rl;
        float acc[8];
#pragma unroll
        for (int q = 0; q < 8; q++) acc[q] = 0.0f;
        if (gr < NN) {
            acc_u4(acc, __ldg(&h16[(size_t)gr * 32 + lane]));
            int j = __ldg(&off[gr]);
            const int je = __ldg(&off[gr + 1]);
            while (j < je) {
                const int cnt = min(32, je - j);
                int myidx = (lane < cnt) ? __ldg(&csr[j + lane]) : 0;
                int e = 0;
                for (; e + 4 <= cnt; e += 4) {
                    int s0 = __shfl_sync(0xFFFFFFFFu, myidx, e);
                    int s1 = __shfl_sync(0xFFFFFFFFu, myidx, e + 1);
                    int s2 = __shfl_sync(0xFFFFFFFFu, myidx, e + 2);
                    int s3 = __shfl_sync(0xFFFFFFFFu, myidx, e + 3);
                    uint4 v0 = __ldg(&h16[(size_t)s0 * 32 + lane]);
                    uint4 v1 = __ldg(&h16[(size_t)s1 * 32 + lane]);
                    uint4 v2 = __ldg(&h16[(size_t)s2 * 32 + lane]);
                    uint4 v3 = __ldg(&h16[(size_t)s3 * 32 + lane]);
                    acc_u4(acc, v0);
                    acc_u4(acc, v1);
                    acc_u4(acc, v2);
                    acc_u4(acc, v3);
                }
                for (; e < cnt; e++) {
                    int s0 = __shfl_sync(0xFFFFFFFFu, myidx, e);
                    acc_u4(acc, __ldg(&h16[(size_t)s0 * 32 + lane]));
                }
                j += cnt;
            }
        }
        // fp16 round; lane owns cols [8*lane, 8*lane+8)
        char* base = smem + (uint32_t)rl * AT_STR + (uint32_t)lane * 16;
        ushort2 h0 = pack_h2(acc[0], acc[1]);
        ushort2 h1 = pack_h2(acc[2], acc[3]);
        ushort2 h2 = pack_h2(acc[4], acc[5]);
        ushort2 h3 = pack_h2(acc[6], acc[7]);
        uint4 hv;
        hv.x = (uint32_t)h0.x | ((uint32_t)h0.y << 16);
        hv.y = (uint32_t)h1.x | ((uint32_t)h1.y << 16);
        hv.z = (uint32_t)h2.x | ((uint32_t)h2.y << 16);
        hv.w = (uint32_t)h3.x | ((uint32_t)h3.y << 16);
        *(uint4*)(base) = hv;
    }
    __syncthreads();

    // phase 1: t = relu(agg @ W1 + b1) -> smem (overwrites A tile)
    gemm_phase<true>(smem, sb, W1h, b1, bm, nullptr, nullptr);
    __syncthreads();

    // phase 2: h = relu(t @ W2 + b2) -> gmem (fp16 hout + fp32 node_embed)
    issue_b_chunk(sb, W2h, 0, 0, tid);
    gemm_phase<false>(smem, sb, W2h, b2, bm, hout, ne);
}

// ---------------------------------------------------------------------------
// Pooling with run compression (batch sorted); reads fp16 layer buffers
// grid (NN/128, 3), blockIdx.y selects the layer buffer.
// ---------------------------------------------------------------------------
__global__ __launch_bounds__(256)
void pool_kernel(const int* __restrict__ batch,
                 const __half* __restrict__ h1, const __half* __restrict__ h2,
                 const __half* __restrict__ h3, float* __restrict__ gev) {
    const int l = blockIdx.y;
    const __half* __restrict__ hb = (l == 0) ? h1 : (l == 1) ? h2 : h3;
    const int c = threadIdx.x;                 // 0..255 within layer block
    const int n0 = blockIdx.x * 128;
    int n1 = n0 + 128; if (n1 > NN) n1 = NN;

    int g = __ldg(&batch[n0]);
    float acc = 0.0f;
    for (int n = n0; n < n1; n++) {
        int gn = __ldg(&batch[n]);
        if (gn != g) {
            atomicAdd(&gev[(size_t)g * ND + l * DD + c], acc);
            acc = 0.0f;
            g = gn;
        }
        acc += __half2float(__ldg(&hb[(size_t)n * DD + c]));
    }
    atomicAdd(&gev[(size_t)g * ND + l * DD + c], acc);
}

__global__ void divide_kernel(float* __restrict__ gev, const int* __restrict__ counts) {
    int i = blockIdx.x * blockDim.x + threadIdx.x;
    if (i >= GG * ND) return;
    int g = i / ND;
    int cnt = counts[g];
    gev[i] *= 1.0f / (float)(cnt > 0 ? cnt : 1);
}

// ---------------------------------------------------------------------------
// Launch
// ---------------------------------------------------------------------------
extern "C" void kernel_launch(void* const* d_in, const int* in_sizes, int n_in,
                              void* d_out, int out_size) {
    const float* x          = (const float*)d_in[0];
    const int*   edge_index = (const int*)d_in[1];
    const int*   batch      = (const int*)d_in[2];
    const float* Ws1        = (const float*)d_in[3];
    const float* bs1        = (const float*)d_in[4];
    const float* Ws2        = (const float*)d_in[5];
    const float* bs2        = (const float*)d_in[6];

    float* out = (float*)d_out;
    float* graph_embed = out;
    float* node_embed  = out + (size_t)GG * ND;

    __half* x16; cudaGetSymbolAddress((void**)&x16, g_x16);
    __half* ha;  cudaGetSymbolAddress((void**)&ha,  g_ha);
    __half* hb;  cudaGetSymbolAddress((void**)&hb,  g_hb);
    __half* hc;  cudaGetSymbolAddress((void**)&hc,  g_hc);
    int* deg;    cudaGetSymbolAddress((void**)&deg, g_deg);
    int* off;    cudaGetSymbolAddress((void**)&off, g_off);
    int* cur;    cudaGetSymbolAddress((void**)&cur, g_cur);
    int* csr;    cudaGetSymbolAddress((void**)&csr, g_csr);
    int* counts; cudaGetSymbolAddress((void**)&counts, g_counts);
    __half* wt;  cudaGetSymbolAddress((void**)&wt,  g_wt);

    cudaFuncSetAttribute(fused_layer_kernel, cudaFuncAttributeMaxDynamicSharedMemorySize, FUSED_SMEM);

    const int* esrc = edge_index;
    const int* edst = edge_index + EE;

    // ---- setup launches ----
    init_zero_kernel<<<(GG * ND + 255) / 256, 256>>>(deg, counts, graph_embed);
    deg_count_kernel<<<(EE + 255) / 256, 256>>>(edst, batch, deg, counts);
    scan_kernel<<<1, 1024>>>(deg, off, cur);
    fill_kernel<<<(EE + 255) / 256, 256>>>(esrc, edst, cur, csr);
    wprep_kernel<<<(6 * 65536 + 255) / 256, 256>>>(Ws1, Ws2, wt);
    xcvt_kernel<<<(NN * DD / 4 + 255) / 256, 256>>>(x, x16);

    const int mtiles = (NN + BM - 1) / BM;   // 782

    // layer chain: x16 -> ha -> hb -> hc (all persist for pooling)
    const __half* hin = x16;
    __half* houts[LL] = {ha, hb, hc};
    for (int l = 0; l < LL; l++) {
        fused_layer_kernel<<<mtiles, 256, FUSED_SMEM>>>(
            hin, off, csr,
            wt + (size_t)l * 65536, bs1 + l * DD,
            wt + (size_t)(3 + l) * 65536, bs2 + l * DD,
            houts[l], node_embed + (size_t)l * DD);
        hin = houts[l];
    }

    dim3 pgrid((NN + 127) / 128, LL);
    pool_kernel<<<pgrid, 256>>>(batch, ha, hb, hc, graph_embed);
    divide_kernel<<<(GG * ND + 255) / 256, 256>>>(graph_embed, counts);
}